// round 12
// baseline (speedup 1.0000x reference)
#include <cuda_runtime.h>
#include <cuda_bf16.h>
#include <math.h>
#include <stdint.h>

#define B_ 32
#define S_ 64
#define T_ 16
#define U_ 1024
#define E_ 256
#define V_ 20200
#define G_ 3072
#define VP_ 20224

// ---------------- device scratch ----------------
__device__ __align__(16) float d_gxall[S_*B_*G_];
__device__ __align__(16) float d_hbuf[2][B_*U_];
__device__ __align__(16) float d_hdec[B_*U_];
__device__ __align__(16) float d_enc[B_*S_*U_];          // [b][s][u]
__device__ __align__(16) float d_pre[B_*S_*U_];          // rows b*64+s
__device__ __align__(16) float d_q[B_*U_];
__device__ __align__(16) float d_gpart[8][B_*G_];
__device__ __align__(16) float d_xcat[B_*U_];
__device__ __align__(16) float d_demb[512*G_];           // rows t*32+b
__device__ __align__(16) float d_Hall[T_*B_*U_];         // rows t*32+b
__device__ __align__(16) float d_logits_alt[T_*B_*V_];
__device__ __align__(16) float d_WhP[U_*G_];
__device__ __align__(16) float d_dWxP[(U_+E_)*G_];
__device__ __align__(16) __nv_bfloat16 d_WfT3[(size_t)3*1024*VP_];
__device__ __align__(16) __nv_bfloat16 d_W1T3[3*1024*1024];
__device__ __align__(16) __nv_bfloat16 d_eWxT3[3*256*G_];
__device__ __align__(16) __nv_bfloat16 d_xembS[2048*768];
__device__ __align__(16) __nv_bfloat16 d_encS[(size_t)2048*3072];   // rows b*64+s
__device__ __align__(16) __nv_bfloat16 d_HallS[512*3072];           // rows t*32+b
__device__ unsigned int d_ctr[3*64];

__device__ __forceinline__ float sigm(float x) { return 1.f / (1.f + expf(-x)); }

// ---------------- setup kernels ----------------
__global__ void perm3(const float* __restrict__ W, float* __restrict__ out) {
    int idx = blockIdx.x * 256 + threadIdx.x;
    int k = idx / G_, c = idx - k * G_;
    int u = c / 3, g = c - u * 3;
    out[idx] = W[(size_t)k * G_ + g * U_ + u];
}

__global__ void embed_split(const int* __restrict__ enc_in, const float* __restrict__ Ee) {
    int idx = blockIdx.x * 256 + threadIdx.x;
    int r = idx >> 8, e = idx & 255;
    int s = r >> 5, b = r & 31;
    float x = Ee[(size_t)enc_in[b * S_ + s] * E_ + e];
    __nv_bfloat16 hi = __float2bfloat16(x);
    __nv_bfloat16 lo = __float2bfloat16(x - __bfloat162float(hi));
    size_t base = (size_t)r * 768;
    d_xembS[base + e] = hi; d_xembS[base + 256 + e] = lo; d_xembS[base + 512 + e] = hi;
}

// A [M][1024] fp32 -> [M][3072] bf16 = [hi|lo|hi] (contiguous rows)
__global__ void conv_splitA(const float* __restrict__ A, __nv_bfloat16* __restrict__ out) {
    int idx = blockIdx.x * 256 + threadIdx.x;
    int m = idx >> 10, k = idx & 1023;
    float x = A[idx];
    __nv_bfloat16 hi = __float2bfloat16(x);
    __nv_bfloat16 lo = __float2bfloat16(x - __bfloat162float(hi));
    size_t base = (size_t)m * 3072;
    out[base + k] = hi; out[base + 1024 + k] = lo; out[base + 2048 + k] = hi;
}

// enc chunk conversion: rows r = b*64 + mofs + sl (512 rows), in/out strided
__global__ void conv_splitA_rm(const float* __restrict__ A, __nv_bfloat16* __restrict__ out, int mofs) {
    int idx = blockIdx.x * 256 + threadIdx.x;        // 512*1024
    int ml = idx >> 10, k = idx & 1023;
    int r = (ml >> 4) * 64 + mofs + (ml & 15);
    float x = A[(size_t)r * 1024 + k];
    __nv_bfloat16 hi = __float2bfloat16(x);
    __nv_bfloat16 lo = __float2bfloat16(x - __bfloat162float(hi));
    size_t base = (size_t)r * 3072;
    out[base + k] = hi; out[base + 1024 + k] = lo; out[base + 2048 + k] = hi;
}

__global__ void conv_splitB_v8(const float* __restrict__ W, __nv_bfloat16* __restrict__ out,
                               int K, int N, int NP) {
    int idx = blockIdx.x * 256 + threadIdx.x;
    int per = NP >> 3;
    int k = idx / per, n = (idx - k * per) * 8;
    if (k >= K) return;
    float v[8];
    if (n + 8 <= N) {
        float4 a = *(const float4*)&W[(size_t)k * N + n];
        float4 b = *(const float4*)&W[(size_t)k * N + n + 4];
        v[0]=a.x; v[1]=a.y; v[2]=a.z; v[3]=a.w; v[4]=b.x; v[5]=b.y; v[6]=b.z; v[7]=b.w;
    } else {
#pragma unroll
        for (int j = 0; j < 8; j++) v[j] = (n + j < N) ? W[(size_t)k * N + n + j] : 0.f;
    }
    __nv_bfloat16 hi[8], lo[8];
#pragma unroll
    for (int j = 0; j < 8; j++) {
        hi[j] = __float2bfloat16(v[j]);
        lo[j] = __float2bfloat16(v[j] - __bfloat162float(hi[j]));
    }
    size_t p = (size_t)k * NP + n, sK = (size_t)K * NP;
    *(uint4*)&out[p]          = *(uint4*)hi;
    *(uint4*)&out[sK + p]     = *(uint4*)hi;
    *(uint4*)&out[2 * sK + p] = *(uint4*)lo;
}

// demb[t*32+b][c] = Ed[teacher[b][t]] @ dWxP[1024:1280][c]
__global__ __launch_bounds__(128) void demb_gemm(
    const float* __restrict__ Ed, const int* __restrict__ teacher,
    const float* __restrict__ dWxP, float* __restrict__ demb)
{
    __shared__ float As[16][32];
    __shared__ float Bs[16][64];
    const int tid = threadIdx.x;
    const int tx = tid & 15, ty = tid >> 4;
    const int n0 = blockIdx.x * 64;
    const int m0 = blockIdx.y * 32;
    float acc[4][4] = {};
    for (int kt = 0; kt < 16; kt++) {
#pragma unroll
        for (int ii = tid; ii < 512; ii += 128) {
            int k = ii & 15, m = ii >> 4;
            int gr = m0 + m, t = gr >> 5, b = gr & 31;
            As[k][m] = Ed[(size_t)teacher[b * T_ + t] * E_ + kt * 16 + k];
        }
#pragma unroll
        for (int ii = tid; ii < 1024; ii += 128) {
            int k = ii >> 6, n = ii & 63;
            Bs[k][n] = dWxP[(size_t)(1024 + kt * 16 + k) * G_ + n0 + n];
        }
        __syncthreads();
#pragma unroll
        for (int kk = 0; kk < 16; kk++) {
            float4 av = *(const float4*)&As[kk][ty * 4];
            float a[4] = {av.x, av.y, av.z, av.w};
#pragma unroll
            for (int j = 0; j < 4; j++) {
                float bv = Bs[kk][tx * 4 + j];
#pragma unroll
                for (int i = 0; i < 4; i++) acc[i][j] += a[i] * bv;
            }
        }
        __syncthreads();
    }
#pragma unroll
    for (int i = 0; i < 4; i++)
#pragma unroll
        for (int j = 0; j < 4; j++)
            demb[(size_t)(m0 + ty * 4 + i) * G_ + n0 + tx * 4 + j] = acc[i][j];
}

// ---------------- tensor-core bf16 GEMM (register-staged prefetch) ----------------
__device__ __forceinline__ void mma_bf16(float* c, const uint32_t* a, const uint32_t* b) {
    asm volatile("mma.sync.aligned.m16n8k16.row.col.f32.bf16.bf16.f32 "
        "{%0,%1,%2,%3},{%4,%5,%6,%7},{%8,%9},{%0,%1,%2,%3};"
        : "+f"(c[0]), "+f"(c[1]), "+f"(c[2]), "+f"(c[3])
        : "r"(a[0]), "r"(a[1]), "r"(a[2]), "r"(a[3]), "r"(b[0]), "r"(b[1]));
}
__device__ __forceinline__ void ldsm_x4(uint32_t* r, uint32_t addr) {
    asm volatile("ldmatrix.sync.aligned.m8n8.x4.shared.b16 {%0,%1,%2,%3}, [%4];"
        : "=r"(r[0]), "=r"(r[1]), "=r"(r[2]), "=r"(r[3]) : "r"(addr));
}
__device__ __forceinline__ void ldsm_x2_trans(uint32_t* r, uint32_t addr) {
    asm volatile("ldmatrix.sync.aligned.m8n8.x2.trans.shared.b16 {%0,%1}, [%2];"
        : "=r"(r[0]), "=r"(r[1]) : "r"(addr));
}

// MODE 0: C[gm*ldC+gc]; MODE 1: logits scatter gg=mofs+gm=t*32+b -> row b*16+t
// MODE 2: row remap r = (gm>>4)*64 + mofs + (gm&15) for BOTH A and C (pre_enc chunks)
template<int MODE>
__global__ __launch_bounds__(256) void gemm_bf16(
    const __nv_bfloat16* __restrict__ A, const __nv_bfloat16* __restrict__ Bkm,
    const float* __restrict__ bias, float* __restrict__ C,
    int ldC, int Nreal, int K3, int ldB, int mofs)
{
    __shared__ __nv_bfloat16 As[2][128 * 40];
    __shared__ __nv_bfloat16 Bs[2][32 * 72];
    const int tid = threadIdx.x;
    const int wid = tid >> 5, lane = tid & 31;
    const int gid = lane >> 2, tig = lane & 3;
    const int wm = wid & 3, wn = wid >> 2;
    const int m0 = blockIdx.y * 128, n0 = blockIdx.x * 64;

    const uint32_t asBase = (uint32_t)__cvta_generic_to_shared(&As[0][0]);
    const uint32_t bsBase = (uint32_t)__cvta_generic_to_shared(&Bs[0][0]);
    const int lquad = lane >> 3, l7 = lane & 7, l15 = lane & 15;
    const uint32_t aLane = (uint32_t)((((lquad & 1) * 8 + l7) * 80) + (lquad >> 1) * 16);

    float acc[2][4][4] = {};
    const int nkt = K3 >> 5;

    const int rowA0 = tid >> 2,          cA0 = tid & 3;
    const int rowA1 = (tid + 256) >> 2,  cA1 = tid & 3;
    const int rB = tid >> 3,             cB = tid & 7;
    int ga0 = m0 + rowA0, ga1 = m0 + rowA1;
    if (MODE == 2) {
        ga0 = (ga0 >> 4) * 64 + mofs + (ga0 & 15);
        ga1 = (ga1 >> 4) * 64 + mofs + (ga1 & 15);
    }

    uint4 ra0, ra1, rb;
    auto ldg = [&](int kt) {
        ra0 = *(const uint4*)&A[(size_t)ga0 * K3 + kt * 32 + cA0 * 8];
        ra1 = *(const uint4*)&A[(size_t)ga1 * K3 + kt * 32 + cA1 * 8];
        rb  = *(const uint4*)&Bkm[(size_t)(kt * 32 + rB) * ldB + n0 + cB * 8];
    };
    auto sts = [&](int buf) {
        *(uint4*)&As[buf][rowA0 * 40 + cA0 * 8] = ra0;
        *(uint4*)&As[buf][rowA1 * 40 + cA1 * 8] = ra1;
        *(uint4*)&Bs[buf][rB * 72 + cB * 8] = rb;
    };

    ldg(0); sts(0);
    __syncthreads();
    for (int kt = 0; kt < nkt; kt++) {
        const int buf = kt & 1;
        if (kt + 1 < nkt) ldg(kt + 1);
#pragma unroll
        for (int ks = 0; ks < 2; ks++) {
            uint32_t a[2][4], b[4][2];
#pragma unroll
            for (int mi = 0; mi < 2; mi++)
                ldsm_x4(a[mi], asBase + (uint32_t)(buf * 128 * 80) +
                               (uint32_t)((wm * 32 + mi * 16) * 80 + ks * 32) + aLane);
#pragma unroll
            for (int ni = 0; ni < 4; ni++)
                ldsm_x2_trans(b[ni], bsBase + (uint32_t)(buf * 32 * 144) +
                              (uint32_t)(((ks * 16 + l15) * 72 + (wn * 32 + ni * 8)) * 2));
#pragma unroll
            for (int mi = 0; mi < 2; mi++)
#pragma unroll
                for (int ni = 0; ni < 4; ni++)
                    mma_bf16(acc[mi][ni], a[mi], b[ni]);
        }
        if (kt + 1 < nkt) sts(buf ^ 1);
        __syncthreads();
    }

#pragma unroll
    for (int mi = 0; mi < 2; mi++)
#pragma unroll
        for (int ni = 0; ni < 4; ni++) {
            int gm0 = m0 + wm * 32 + mi * 16 + gid;
            int gc0 = n0 + wn * 32 + ni * 8 + tig * 2;
#pragma unroll
            for (int e = 0; e < 4; e++) {
                int gm = gm0 + (e >> 1) * 8;
                int gc = gc0 + (e & 1);
                float v = acc[mi][ni][e];
                if (MODE == 1) {
                    if (gc < Nreal) {
                        int gg = mofs + gm;
                        int bb = gg & 31, tt = gg >> 5;
                        C[(size_t)(bb * T_ + tt) * Nreal + gc] = v + bias[gc];
                    }
                } else if (MODE == 2) {
                    int r = (gm >> 4) * 64 + mofs + (gm & 15);
                    C[(size_t)r * ldC + gc] = v + bias[gc];
                } else {
                    C[(size_t)gm * ldC + gc] = v + bias[gc];
                }
            }
        }
}

// ---------------- fused recurrence step ----------------
template<int BN, int TN, int NKC, int GATE>
__global__ __launch_bounds__(128) void step_gemm(
    const float* __restrict__ A, const float* __restrict__ Bm,
    const float* __restrict__ xb, const float* __restrict__ hb,
    const float* __restrict__ hin, float* __restrict__ hout,
    float* __restrict__ extra, float* __restrict__ part,
    float* __restrict__ qout, unsigned int* __restrict__ ctr,
    int N, int K)
{
    constexpr int PB = (16 * BN) / 128;
    __shared__ float As[16][32];
    __shared__ float Bs[16][BN];
    __shared__ int doneflag;
    const int tid = threadIdx.x;
    const int tx = tid & 15, ty = tid >> 4;
    const int n0 = blockIdx.x * BN;
    const int z = blockIdx.z;
    const int k0 = z * NKC * 16;

    float pa[4], pb[PB];
    auto ldA = [&](int kt) {
#pragma unroll
        for (int i = 0; i < 4; i++) {
            int ii = tid + i * 128, k = ii & 15, m = ii >> 4;
            pa[i] = A[(size_t)m * K + k0 + kt * 16 + k];
        }
    };
    auto ldB = [&](int kt) {
#pragma unroll
        for (int i = 0; i < PB; i++) {
            int ii = tid + i * 128, k = ii / BN, n = ii - k * BN;
            pb[i] = Bm[(size_t)(k0 + kt * 16 + k) * N + n0 + n];
        }
    };

    float acc[4][TN];
#pragma unroll
    for (int i = 0; i < 4; i++)
#pragma unroll
        for (int j = 0; j < TN; j++) acc[i][j] = 0.f;

    ldA(0); ldB(0);
    for (int kt = 0; kt < NKC; kt++) {
#pragma unroll
        for (int i = 0; i < 4; i++) {
            int ii = tid + i * 128;
            As[ii & 15][ii >> 4] = pa[i];
        }
#pragma unroll
        for (int i = 0; i < PB; i++) {
            int ii = tid + i * 128, k = ii / BN;
            Bs[k][ii - k * BN] = pb[i];
        }
        __syncthreads();
        if (kt + 1 < NKC) { ldA(kt + 1); ldB(kt + 1); }
#pragma unroll
        for (int kk = 0; kk < 16; kk++) {
            float4 av = *reinterpret_cast<const float4*>(&As[kk][ty * 4]);
            float a[4] = {av.x, av.y, av.z, av.w};
#pragma unroll
            for (int j = 0; j < TN; j++) {
                float bv = Bs[kk][tx * TN + j];
#pragma unroll
                for (int i = 0; i < 4; i++) acc[i][j] += a[i] * bv;
            }
        }
        __syncthreads();
    }
#pragma unroll
    for (int i = 0; i < 4; i++) {
        int gm = ty * 4 + i;
#pragma unroll
        for (int j = 0; j < TN; j++)
            part[((size_t)(z * 32 + gm)) * N + n0 + tx * TN + j] = acc[i][j];
    }
    __threadfence();
    __syncthreads();
    if (tid == 0) {
        unsigned int prev = atomicAdd(&ctr[blockIdx.x], 1u);
        doneflag = (prev == 7u);
        if (prev == 7u) ctr[blockIdx.x] = 0u;
    }
    __syncthreads();
    if (!doneflag) return;
    __threadfence();

    if (GATE == 0) {
#pragma unroll
        for (int i = 0; i < 16; i++) {
            int idx = tid + i * 128;
            int b = idx & 31, nl = idx >> 5;
            int n = n0 + nl;
            float s = 0.f;
#pragma unroll
            for (int zz = 0; zz < 8; zz++) s += part[((size_t)(zz * 32 + b)) * N + n];
            qout[b * U_ + n] = s + hb[n];
        }
    } else {
        const int u0 = n0 / 3;
#pragma unroll
        for (int i = 0; i < 4; i++) {
            int idx = tid + i * 128;
            int b = idx & 31, ul = idx >> 5;
            int u = u0 + ul;
            float g[3];
#pragma unroll
            for (int gg = 0; gg < 3; gg++) {
                float s = 0.f;
#pragma unroll
                for (int zz = 0; zz < 8; zz++)
                    s += part[((size_t)(zz * 32 + b)) * N + n0 + ul * 3 + gg];
                g[gg] = s;
            }
            float h;
            if (GATE == 1) {
                const float* gx = xb + (size_t)b * G_;
                float zg = sigm(gx[u] + g[0] + hb[u]);
                float rg = sigm(gx[U_ + u] + g[1] + hb[U_ + u]);
                float cg = tanhf(gx[2 * U_ + u] + rg * (g[2] + hb[2 * U_ + u]));
                h = zg * hin[b * U_ + u] + (1.f - zg) * cg;
                hout[b * U_ + u] = h;
                extra[(size_t)b * (S_ * U_) + u] = h;
            } else {
                const float* de = hin + (size_t)b * G_ + n0 + ul * 3;
                float zg = sigm(g[0] + de[0] + xb[u] + hb[u]);
                float rg = sigm(g[1] + de[1] + xb[U_ + u] + hb[U_ + u]);
                float cg = tanhf(g[2] + de[2] + xb[2 * U_ + u] + rg * hb[2 * U_ + u]);
                h = (1.f - zg) * cg;
                hout[b * U_ + u] = h;
                extra[(size_t)b * U_ + u] = h;
            }
        }
    }
}

// ---------------- attention + context ----------------
__global__ void attn_ctx(const float* __restrict__ Va, const float* __restrict__ bvp)
{
    const int b = blockIdx.x, tid = threadIdx.x;
    __shared__ float qs[U_];
    __shared__ float sc[S_];

    for (int u = tid; u < U_; u += 512) qs[u] = d_q[b * U_ + u];
    __syncthreads();

    const int w = tid >> 5, lane = tid & 31;
    for (int s = w; s < S_; s += 16) {
        const float* pr = d_pre + (size_t)b * (S_ * U_) + (size_t)s * U_;
        float p = 0.f;
        for (int u = lane; u < U_; u += 32) p += tanhf(pr[u] + qs[u]) * Va[u];
#pragma unroll
        for (int o = 16; o > 0; o >>= 1) p += __shfl_xor_sync(0xffffffffu, p, o);
        if (lane == 0) sc[s] = p + bvp[0];
    }
    __syncthreads();

    if (tid < 32) {
        float v0 = sc[tid], v1 = sc[tid + 32];
        float m = fmaxf(v0, v1);
#pragma unroll
        for (int o = 16; o > 0; o >>= 1) m = fmaxf(m, __shfl_xor_sync(0xffffffffu, m, o));
        float e0 = expf(v0 - m), e1 = expf(v1 - m);
        float s = e0 + e1;
#pragma unroll
        for (int o = 16; o > 0; o >>= 1) s += __shfl_xor_sync(0xffffffffu, s, o);
        float inv = 1.f / s;
        sc[tid] = e0 * inv; sc[tid + 32] = e1 * inv;
    }
    __syncthreads();

    for (int u = tid; u < U_; u += 512) {
        float a = 0.f;
        const float* eb = d_enc + (size_t)b * (S_ * U_) + u;
#pragma unroll 8
        for (int s = 0; s < S_; s++) a += sc[s] * eb[(size_t)s * U_];
        d_xcat[(size_t)b * U_ + u] = a;
    }
}

// ---------------- argmax ----------------
__global__ void argmax_k(const float* __restrict__ logits, long long* outI, float* outF, int asFloat)
{
    const int row = blockIdx.x;
    const float* p = logits + (size_t)row * V_;
    const int tid = threadIdx.x;
    float best = -INFINITY; int bi = 0;
    for (int v = tid; v < V_; v += 256) {
        float val = p[v];
        if (val > best) { best = val; bi = v; }
    }
    __shared__ float bvs[256]; __shared__ int bis[256];
    bvs[tid] = best; bis[tid] = bi;
    __syncthreads();
    for (int st = 128; st > 0; st >>= 1) {
        if (tid < st) {
            float ov = bvs[tid + st]; int oi = bis[tid + st];
            if (ov > bvs[tid] || (ov == bvs[tid] && oi < bis[tid])) { bvs[tid] = ov; bis[tid] = oi; }
        }
        __syncthreads();
    }
    if (tid == 0) {
        if (asFloat) outF[row] = (float)bis[0];
        else         outI[row] = (long long)bis[0];
    }
}

// ---------------- launcher ----------------
static float* symaddr(const void* sym) {
    void* p = nullptr;
    cudaGetSymbolAddress(&p, sym);
    return (float*)p;
}

extern "C" void kernel_launch(void* const* d_in, const int* in_sizes, int n_in,
                              void* d_out, int out_size)
{
    static cudaStream_t s2 = nullptr;
    static cudaEvent_t ev[16];
    if (!s2) {
        cudaStreamCreateWithFlags(&s2, cudaStreamNonBlocking);
        for (int i = 0; i < 16; i++) cudaEventCreateWithFlags(&ev[i], cudaEventDisableTiming);
    }

    const int s0 = (n_in >= 22) ? 4 : 2;
    const int*   enc_in  = (const int*)d_in[0];
    const int*   teacher = (const int*)d_in[1];
    const float* Ee      = (const float*)d_in[s0 + 0];
    const float* eWx     = (const float*)d_in[s0 + 1];
    const float* eWh     = (const float*)d_in[s0 + 2];
    const float* eb_in   = (const float*)d_in[s0 + 3];
    const float* eb_rec  = (const float*)d_in[s0 + 4];
    const float* Ed      = (const float*)d_in[s0 + 5];
    const float* dWx     = (const float*)d_in[s0 + 6];
    const float* db_in   = (const float*)d_in[s0 + 8];
    const float* db_rec  = (const float*)d_in[s0 + 9];
    const float* W1      = (const float*)d_in[s0 + 10];
    const float* b1      = (const float*)d_in[s0 + 11];
    const float* W2      = (const float*)d_in[s0 + 12];
    const float* b2      = (const float*)d_in[s0 + 13];
    const float* Va      = (const float*)d_in[s0 + 14];
    const float* bvp     = (const float*)d_in[s0 + 15];
    const float* Wf      = (const float*)d_in[s0 + 16];
    const float* bf      = (const float*)d_in[s0 + 17];

    float* hbase = symaddr(d_hbuf);
    float* hdec  = symaddr(d_hdec);
    float* encp  = symaddr(d_enc);
    float* prep  = symaddr(d_pre);
    float* qp    = symaddr(d_q);
    float* gpart = symaddr(d_gpart);
    float* xcat  = symaddr(d_xcat);
    float* demb  = symaddr(d_demb);
    float* Hall  = symaddr(d_Hall);
    float* lalt  = symaddr(d_logits_alt);
    float* gxall = symaddr(d_gxall);
    float* WhP   = symaddr(d_WhP);
    float* dWxP  = symaddr(d_dWxP);
    unsigned int* ctr; { void* p; cudaGetSymbolAddress(&p, d_ctr); ctr = (unsigned int*)p; }
    __nv_bfloat16* WfT3;  { void* p; cudaGetSymbolAddress(&p, d_WfT3);  WfT3  = (__nv_bfloat16*)p; }
    __nv_bfloat16* W1T3;  { void* p; cudaGetSymbolAddress(&p, d_W1T3);  W1T3  = (__nv_bfloat16*)p; }
    __nv_bfloat16* eWxT3; { void* p; cudaGetSymbolAddress(&p, d_eWxT3); eWxT3 = (__nv_bfloat16*)p; }
    __nv_bfloat16* xembS; { void* p; cudaGetSymbolAddress(&p, d_xembS); xembS = (__nv_bfloat16*)p; }
    __nv_bfloat16* encS;  { void* p; cudaGetSymbolAddress(&p, d_encS);  encS  = (__nv_bfloat16*)p; }
    __nv_bfloat16* HallS; { void* p; cudaGetSymbolAddress(&p, d_HallS); HallS = (__nv_bfloat16*)p; }

    const long long LOGN = (long long)B_ * T_ * V_;
    float* logits_dst = (float*)d_out;
    long long* predI = nullptr; float* predF = nullptr; int asFloat = 0;
    if ((long long)out_size == LOGN + 512) { predF = (float*)d_out + LOGN; asFloat = 1; }
    else if ((long long)out_size == LOGN + 1024) { predI = (long long*)((float*)d_out + LOGN); }
    else if (out_size == 512) { logits_dst = lalt; predI = (long long*)d_out; }

    cudaMemsetAsync(hbase, 0, (size_t)B_ * U_ * sizeof(float));

    // fork s2: eWx split, embed, gx chunks 0-3, W1 split, dWx perm+demb, Wf split
    cudaEventRecord(ev[0], 0);
    cudaStreamWaitEvent(s2, ev[0], 0);
    conv_splitB_v8<<<(E_ * (G_ / 8) + 255) / 256, 256, 0, s2>>>(eWx, eWxT3, E_, G_, G_);
    embed_split<<<2048, 256, 0, s2>>>(enc_in, Ee);
    for (int c = 0; c < 4; c++) {
        gemm_bf16<0><<<dim3(G_ / 64, 4), 256, 0, s2>>>(
            xembS + (size_t)c * 512 * 768, eWxT3, eb_in,
            gxall + (size_t)c * 512 * G_, G_, G_, 768, G_, 0);
        cudaEventRecord(ev[1 + c], s2);             // gx chunk c ready
    }
    conv_splitB_v8<<<(U_ * (U_ / 8) + 255) / 256, 256, 0, s2>>>(W1, W1T3, U_, U_, U_);
    perm3<<<(U_ + E_) * G_ / 256, 256, 0, s2>>>(dWx, dWxP);
    demb_gemm<<<dim3(G_ / 64, 16), 128, 0, s2>>>(Ed, teacher, dWxP, demb);
    cudaEventRecord(ev[5], s2);                     // dWxP + demb ready
    conv_splitB_v8<<<(U_ * (VP_ / 8) + 255) / 256, 256, 0, s2>>>(Wf, WfT3, U_, V_, VP_);

    // main: eWh permute, then encoder recurrence
    perm3<<<U_ * G_ / 256, 256>>>(eWh, WhP);
    for (int s = 0; s < S_; s++) {
        if ((s & 15) == 0) cudaStreamWaitEvent(0, ev[1 + (s >> 4)], 0);
        float* hin  = hbase + (size_t)(s & 1) * B_ * U_;
        float* hout = hbase + (size_t)((s + 1) & 1) * B_ * U_;
        step_gemm<48,3,8,1><<<dim3(G_ / 48, 1, 8), 128>>>(
            hin, WhP, gxall + (size_t)s * B_ * G_, eb_rec,
            hin, hout, encp + (size_t)s * U_, gpart, nullptr, ctr, G_, U_);
        if ((s & 15) == 15) cudaEventRecord(ev[6 + (s >> 4)], 0);  // enc chunk done
    }

    // pre_enc chunks on s2 (hidden behind encoder)
    for (int c = 0; c < 4; c++) {
        cudaStreamWaitEvent(s2, ev[6 + c], 0);
        conv_splitA_rm<<<2048, 256, 0, s2>>>(encp, encS, 16 * c);
        gemm_bf16<2><<<dim3(U_ / 64, 4), 256, 0, s2>>>(encS, W1T3, b1, prep,
                                                       U_, U_, 3072, U_, 16 * c);
    }
    cudaEventRecord(ev[10], s2);                    // d_pre ready

    // decoder
    cudaStreamWaitEvent(0, ev[5], 0);
    cudaStreamWaitEvent(0, ev[10], 0);
    for (int t = 0; t < T_; t++) {
        const float* hd = (t == 0) ? hbase : hdec;
        step_gemm<64,4,8,0><<<dim3(U_ / 64, 1, 8), 128>>>(
            hd, W2, nullptr, b2, nullptr, nullptr, nullptr, gpart, qp, ctr + 64, U_, U_);
        attn_ctx<<<B_, 512>>>(Va, bvp);
        step_gemm<48,3,8,2><<<dim3(G_ / 48, 1, 8), 128>>>(
            xcat, dWxP, db_in, db_rec, demb + (size_t)t * 32 * G_, hdec,
            Hall + (size_t)t * B_ * U_, gpart, nullptr, ctr + 128, G_, U_);
        if ((t & 3) == 3) {
            int c = t >> 2;
            cudaEventRecord(ev[11 + c], 0);
            cudaStreamWaitEvent(s2, ev[11 + c], 0);
            conv_splitA<<<512, 256, 0, s2>>>(Hall + (size_t)c * 128 * U_,
                                             HallS + (size_t)c * 128 * 3072);
            gemm_bf16<1><<<dim3(VP_ / 64, 1), 256, 0, s2>>>(
                HallS + (size_t)c * 128 * 3072, WfT3, bf, logits_dst, 0, V_, 3072, VP_, c * 128);
        }
    }

    // join, argmax
    cudaEventRecord(ev[15], s2);
    cudaStreamWaitEvent(0, ev[15], 0);
    if (predI || predF) argmax_k<<<T_ * B_, 256>>>(logits_dst, predI, predF, asFloat);
}

// round 13
// speedup vs baseline: 1.0160x; 1.0160x over previous
#include <cuda_runtime.h>
#include <cuda_bf16.h>
#include <math.h>
#include <stdint.h>

#define B_ 32
#define S_ 64
#define T_ 16
#define U_ 1024
#define E_ 256
#define V_ 20200
#define G_ 3072
#define VP_ 20224

// ---------------- device scratch ----------------
__device__ __align__(16) float d_gxall[S_*B_*G_];
__device__ __align__(16) float d_hbuf[2][B_*U_];
__device__ __align__(16) float d_hdec[B_*U_];
__device__ __align__(16) float d_enc[B_*S_*U_];          // [b][s][u]
__device__ __align__(16) float d_pre[B_*S_*U_];          // rows b*64+s
__device__ __align__(16) float d_q[B_*U_];
__device__ __align__(16) float d_gpart[8][B_*G_];
__device__ __align__(16) float d_xcat[B_*U_];
__device__ __align__(16) float d_demb[512*G_];           // rows t*32+b
__device__ __align__(16) float d_Hall[T_*B_*U_];         // rows t*32+b
__device__ __align__(16) float d_logits_alt[T_*B_*V_];
__device__ __align__(16) float d_WhP[U_*G_];
__device__ __align__(16) float d_dWxP[(U_+E_)*G_];
__device__ __align__(16) __nv_bfloat16 d_WfT3[(size_t)3*1024*VP_];
__device__ __align__(16) __nv_bfloat16 d_W1T3[3*1024*1024];
__device__ __align__(16) __nv_bfloat16 d_eWxT3[3*256*G_];
__device__ __align__(16) __nv_bfloat16 d_xembS[2048*768];
__device__ __align__(16) __nv_bfloat16 d_encS[(size_t)2048*3072];   // rows b*64+s
__device__ __align__(16) __nv_bfloat16 d_HallS[512*3072];           // rows t*32+b
__device__ unsigned int d_ctr[3*64];

__device__ __forceinline__ float sigm(float x) { return 1.f / (1.f + expf(-x)); }

// ---------------- setup kernels ----------------
__global__ void perm3(const float* __restrict__ W, float* __restrict__ out) {
    int idx = blockIdx.x * 256 + threadIdx.x;
    int k = idx / G_, c = idx - k * G_;
    int u = c / 3, g = c - u * 3;
    out[idx] = W[(size_t)k * G_ + g * U_ + u];
}

__global__ void embed_split(const int* __restrict__ enc_in, const float* __restrict__ Ee) {
    int idx = blockIdx.x * 256 + threadIdx.x;
    int r = idx >> 8, e = idx & 255;
    int s = r >> 5, b = r & 31;
    float x = Ee[(size_t)enc_in[b * S_ + s] * E_ + e];
    __nv_bfloat16 hi = __float2bfloat16(x);
    __nv_bfloat16 lo = __float2bfloat16(x - __bfloat162float(hi));
    size_t base = (size_t)r * 768;
    d_xembS[base + e] = hi; d_xembS[base + 256 + e] = lo; d_xembS[base + 512 + e] = hi;
}

// A [M][1024] fp32 -> [M][3072] bf16 = [hi|lo|hi]
__global__ void conv_splitA(const float* __restrict__ A, __nv_bfloat16* __restrict__ out) {
    int idx = blockIdx.x * 256 + threadIdx.x;
    int m = idx >> 10, k = idx & 1023;
    float x = A[idx];
    __nv_bfloat16 hi = __float2bfloat16(x);
    __nv_bfloat16 lo = __float2bfloat16(x - __bfloat162float(hi));
    size_t base = (size_t)m * 3072;
    out[base + k] = hi; out[base + 1024 + k] = lo; out[base + 2048 + k] = hi;
}

__global__ void conv_splitB_v8(const float* __restrict__ W, __nv_bfloat16* __restrict__ out,
                               int K, int N, int NP) {
    int idx = blockIdx.x * 256 + threadIdx.x;
    int per = NP >> 3;
    int k = idx / per, n = (idx - k * per) * 8;
    if (k >= K) return;
    float v[8];
    if (n + 8 <= N) {
        float4 a = *(const float4*)&W[(size_t)k * N + n];
        float4 b = *(const float4*)&W[(size_t)k * N + n + 4];
        v[0]=a.x; v[1]=a.y; v[2]=a.z; v[3]=a.w; v[4]=b.x; v[5]=b.y; v[6]=b.z; v[7]=b.w;
    } else {
#pragma unroll
        for (int j = 0; j < 8; j++) v[j] = (n + j < N) ? W[(size_t)k * N + n + j] : 0.f;
    }
    __nv_bfloat16 hi[8], lo[8];
#pragma unroll
    for (int j = 0; j < 8; j++) {
        hi[j] = __float2bfloat16(v[j]);
        lo[j] = __float2bfloat16(v[j] - __bfloat162float(hi[j]));
    }
    size_t p = (size_t)k * NP + n, sK = (size_t)K * NP;
    *(uint4*)&out[p]          = *(uint4*)hi;
    *(uint4*)&out[sK + p]     = *(uint4*)hi;
    *(uint4*)&out[2 * sK + p] = *(uint4*)lo;
}

// demb[t*32+b][c] = Ed[teacher[b][t]] @ dWxP[1024:1280][c]
__global__ __launch_bounds__(128) void demb_gemm(
    const float* __restrict__ Ed, const int* __restrict__ teacher,
    const float* __restrict__ dWxP, float* __restrict__ demb)
{
    __shared__ float As[16][32];
    __shared__ float Bs[16][64];
    const int tid = threadIdx.x;
    const int tx = tid & 15, ty = tid >> 4;
    const int n0 = blockIdx.x * 64;
    const int m0 = blockIdx.y * 32;
    float acc[4][4] = {};
    for (int kt = 0; kt < 16; kt++) {
#pragma unroll
        for (int ii = tid; ii < 512; ii += 128) {
            int k = ii & 15, m = ii >> 4;
            int gr = m0 + m, t = gr >> 5, b = gr & 31;
            As[k][m] = Ed[(size_t)teacher[b * T_ + t] * E_ + kt * 16 + k];
        }
#pragma unroll
        for (int ii = tid; ii < 1024; ii += 128) {
            int k = ii >> 6, n = ii & 63;
            Bs[k][n] = dWxP[(size_t)(1024 + kt * 16 + k) * G_ + n0 + n];
        }
        __syncthreads();
#pragma unroll
        for (int kk = 0; kk < 16; kk++) {
            float4 av = *(const float4*)&As[kk][ty * 4];
            float a[4] = {av.x, av.y, av.z, av.w};
#pragma unroll
            for (int j = 0; j < 4; j++) {
                float bv = Bs[kk][tx * 4 + j];
#pragma unroll
                for (int i = 0; i < 4; i++) acc[i][j] += a[i] * bv;
            }
        }
        __syncthreads();
    }
#pragma unroll
    for (int i = 0; i < 4; i++)
#pragma unroll
        for (int j = 0; j < 4; j++)
            demb[(size_t)(m0 + ty * 4 + i) * G_ + n0 + tx * 4 + j] = acc[i][j];
}

// ---------------- tensor-core bf16 GEMM (register-staged prefetch) ----------------
__device__ __forceinline__ void mma_bf16(float* c, const uint32_t* a, const uint32_t* b) {
    asm volatile("mma.sync.aligned.m16n8k16.row.col.f32.bf16.bf16.f32 "
        "{%0,%1,%2,%3},{%4,%5,%6,%7},{%8,%9},{%0,%1,%2,%3};"
        : "+f"(c[0]), "+f"(c[1]), "+f"(c[2]), "+f"(c[3])
        : "r"(a[0]), "r"(a[1]), "r"(a[2]), "r"(a[3]), "r"(b[0]), "r"(b[1]));
}
__device__ __forceinline__ void ldsm_x4(uint32_t* r, uint32_t addr) {
    asm volatile("ldmatrix.sync.aligned.m8n8.x4.shared.b16 {%0,%1,%2,%3}, [%4];"
        : "=r"(r[0]), "=r"(r[1]), "=r"(r[2]), "=r"(r[3]) : "r"(addr));
}
__device__ __forceinline__ void ldsm_x2_trans(uint32_t* r, uint32_t addr) {
    asm volatile("ldmatrix.sync.aligned.m8n8.x2.trans.shared.b16 {%0,%1}, [%2];"
        : "=r"(r[0]), "=r"(r[1]) : "r"(addr));
}

// MODE 0: C[gm*ldC+gc]; MODE 1: logits scatter gg=mofs+gm=t*32+b -> row b*16+t
template<int MODE>
__global__ __launch_bounds__(256) void gemm_bf16(
    const __nv_bfloat16* __restrict__ A, const __nv_bfloat16* __restrict__ Bkm,
    const float* __restrict__ bias, float* __restrict__ C,
    int ldC, int Nreal, int K3, int ldB, int mofs)
{
    __shared__ __nv_bfloat16 As[2][128 * 40];
    __shared__ __nv_bfloat16 Bs[2][32 * 72];
    const int tid = threadIdx.x;
    const int wid = tid >> 5, lane = tid & 31;
    const int gid = lane >> 2, tig = lane & 3;
    const int wm = wid & 3, wn = wid >> 2;
    const int m0 = blockIdx.y * 128, n0 = blockIdx.x * 64;

    const uint32_t asBase = (uint32_t)__cvta_generic_to_shared(&As[0][0]);
    const uint32_t bsBase = (uint32_t)__cvta_generic_to_shared(&Bs[0][0]);
    const int lquad = lane >> 3, l7 = lane & 7, l15 = lane & 15;
    const uint32_t aLane = (uint32_t)((((lquad & 1) * 8 + l7) * 80) + (lquad >> 1) * 16);

    float acc[2][4][4] = {};
    const int nkt = K3 >> 5;

    const int rowA0 = tid >> 2,          cA0 = tid & 3;
    const int rowA1 = (tid + 256) >> 2,  cA1 = tid & 3;
    const int rB = tid >> 3,             cB = tid & 7;
    const int ga0 = m0 + rowA0, ga1 = m0 + rowA1;

    uint4 ra0, ra1, rb;
    auto ldg = [&](int kt) {
        ra0 = *(const uint4*)&A[(size_t)ga0 * K3 + kt * 32 + cA0 * 8];
        ra1 = *(const uint4*)&A[(size_t)ga1 * K3 + kt * 32 + cA1 * 8];
        rb  = *(const uint4*)&Bkm[(size_t)(kt * 32 + rB) * ldB + n0 + cB * 8];
    };
    auto sts = [&](int buf) {
        *(uint4*)&As[buf][rowA0 * 40 + cA0 * 8] = ra0;
        *(uint4*)&As[buf][rowA1 * 40 + cA1 * 8] = ra1;
        *(uint4*)&Bs[buf][rB * 72 + cB * 8] = rb;
    };

    ldg(0); sts(0);
    __syncthreads();
    for (int kt = 0; kt < nkt; kt++) {
        const int buf = kt & 1;
        if (kt + 1 < nkt) ldg(kt + 1);
#pragma unroll
        for (int ks = 0; ks < 2; ks++) {
            uint32_t a[2][4], b[4][2];
#pragma unroll
            for (int mi = 0; mi < 2; mi++)
                ldsm_x4(a[mi], asBase + (uint32_t)(buf * 128 * 80) +
                               (uint32_t)((wm * 32 + mi * 16) * 80 + ks * 32) + aLane);
#pragma unroll
            for (int ni = 0; ni < 4; ni++)
                ldsm_x2_trans(b[ni], bsBase + (uint32_t)(buf * 32 * 144) +
                              (uint32_t)(((ks * 16 + l15) * 72 + (wn * 32 + ni * 8)) * 2));
#pragma unroll
            for (int mi = 0; mi < 2; mi++)
#pragma unroll
                for (int ni = 0; ni < 4; ni++)
                    mma_bf16(acc[mi][ni], a[mi], b[ni]);
        }
        if (kt + 1 < nkt) sts(buf ^ 1);
        __syncthreads();
    }

#pragma unroll
    for (int mi = 0; mi < 2; mi++)
#pragma unroll
        for (int ni = 0; ni < 4; ni++) {
            int gm0 = m0 + wm * 32 + mi * 16 + gid;
            int gc0 = n0 + wn * 32 + ni * 8 + tig * 2;
#pragma unroll
            for (int e = 0; e < 4; e++) {
                int gm = gm0 + (e >> 1) * 8;
                int gc = gc0 + (e & 1);
                float v = acc[mi][ni][e];
                if (MODE == 1) {
                    if (gc < Nreal) {
                        int gg = mofs + gm;
                        int bb = gg & 31, tt = gg >> 5;
                        C[(size_t)(bb * T_ + tt) * Nreal + gc] = v + bias[gc];
                    }
                } else {
                    C[(size_t)gm * ldC + gc] = v + bias[gc];
                }
            }
        }
}

// ---------------- fused recurrence step ----------------
template<int BN, int TN, int NKC, int GATE>
__global__ __launch_bounds__(128) void step_gemm(
    const float* __restrict__ A, const float* __restrict__ Bm,
    const float* __restrict__ xb, const float* __restrict__ hb,
    const float* __restrict__ hin, float* __restrict__ hout,
    float* __restrict__ extra, float* __restrict__ part,
    float* __restrict__ qout, unsigned int* __restrict__ ctr,
    int N, int K)
{
    constexpr int PB = (16 * BN) / 128;
    __shared__ float As[16][32];
    __shared__ float Bs[16][BN];
    __shared__ int doneflag;
    const int tid = threadIdx.x;
    const int tx = tid & 15, ty = tid >> 4;
    const int n0 = blockIdx.x * BN;
    const int z = blockIdx.z;
    const int k0 = z * NKC * 16;

    float pa[4], pb[PB];
    auto ldA = [&](int kt) {
#pragma unroll
        for (int i = 0; i < 4; i++) {
            int ii = tid + i * 128, k = ii & 15, m = ii >> 4;
            pa[i] = A[(size_t)m * K + k0 + kt * 16 + k];
        }
    };
    auto ldB = [&](int kt) {
#pragma unroll
        for (int i = 0; i < PB; i++) {
            int ii = tid + i * 128, k = ii / BN, n = ii - k * BN;
            pb[i] = Bm[(size_t)(k0 + kt * 16 + k) * N + n0 + n];
        }
    };

    float acc[4][TN];
#pragma unroll
    for (int i = 0; i < 4; i++)
#pragma unroll
        for (int j = 0; j < TN; j++) acc[i][j] = 0.f;

    ldA(0); ldB(0);
    for (int kt = 0; kt < NKC; kt++) {
#pragma unroll
        for (int i = 0; i < 4; i++) {
            int ii = tid + i * 128;
            As[ii & 15][ii >> 4] = pa[i];
        }
#pragma unroll
        for (int i = 0; i < PB; i++) {
            int ii = tid + i * 128, k = ii / BN;
            Bs[k][ii - k * BN] = pb[i];
        }
        __syncthreads();
        if (kt + 1 < NKC) { ldA(kt + 1); ldB(kt + 1); }
#pragma unroll
        for (int kk = 0; kk < 16; kk++) {
            float4 av = *reinterpret_cast<const float4*>(&As[kk][ty * 4]);
            float a[4] = {av.x, av.y, av.z, av.w};
#pragma unroll
            for (int j = 0; j < TN; j++) {
                float bv = Bs[kk][tx * TN + j];
#pragma unroll
                for (int i = 0; i < 4; i++) acc[i][j] += a[i] * bv;
            }
        }
        __syncthreads();
    }
#pragma unroll
    for (int i = 0; i < 4; i++) {
        int gm = ty * 4 + i;
#pragma unroll
        for (int j = 0; j < TN; j++)
            part[((size_t)(z * 32 + gm)) * N + n0 + tx * TN + j] = acc[i][j];
    }
    __threadfence();
    __syncthreads();
    if (tid == 0) {
        unsigned int prev = atomicAdd(&ctr[blockIdx.x], 1u);
        doneflag = (prev == 7u);
        if (prev == 7u) ctr[blockIdx.x] = 0u;
    }
    __syncthreads();
    if (!doneflag) return;
    __threadfence();

    if (GATE == 0) {
#pragma unroll
        for (int i = 0; i < 16; i++) {
            int idx = tid + i * 128;
            int b = idx & 31, nl = idx >> 5;
            int n = n0 + nl;
            float s = 0.f;
#pragma unroll
            for (int zz = 0; zz < 8; zz++) s += part[((size_t)(zz * 32 + b)) * N + n];
            qout[b * U_ + n] = s + hb[n];
        }
    } else {
        const int u0 = n0 / 3;
#pragma unroll
        for (int i = 0; i < 4; i++) {
            int idx = tid + i * 128;
            int b = idx & 31, ul = idx >> 5;
            int u = u0 + ul;
            float g[3];
#pragma unroll
            for (int gg = 0; gg < 3; gg++) {
                float s = 0.f;
#pragma unroll
                for (int zz = 0; zz < 8; zz++)
                    s += part[((size_t)(zz * 32 + b)) * N + n0 + ul * 3 + gg];
                g[gg] = s;
            }
            float h;
            if (GATE == 1) {
                const float* gx = xb + (size_t)b * G_;
                float zg = sigm(gx[u] + g[0] + hb[u]);
                float rg = sigm(gx[U_ + u] + g[1] + hb[U_ + u]);
                float cg = tanhf(gx[2 * U_ + u] + rg * (g[2] + hb[2 * U_ + u]));
                h = zg * hin[b * U_ + u] + (1.f - zg) * cg;
                hout[b * U_ + u] = h;
                extra[(size_t)b * (S_ * U_) + u] = h;
            } else {
                const float* de = hin + (size_t)b * G_ + n0 + ul * 3;
                float zg = sigm(g[0] + de[0] + xb[u] + hb[u]);
                float rg = sigm(g[1] + de[1] + xb[U_ + u] + hb[U_ + u]);
                float cg = tanhf(g[2] + de[2] + xb[2 * U_ + u] + rg * hb[2 * U_ + u]);
                h = (1.f - zg) * cg;
                hout[b * U_ + u] = h;
                extra[(size_t)b * U_ + u] = h;
            }
        }
    }
}

// ---------------- attention + context ----------------
__global__ void attn_ctx(const float* __restrict__ Va, const float* __restrict__ bvp)
{
    const int b = blockIdx.x, tid = threadIdx.x;
    __shared__ float qs[U_];
    __shared__ float sc[S_];

    for (int u = tid; u < U_; u += 512) qs[u] = d_q[b * U_ + u];
    __syncthreads();

    const int w = tid >> 5, lane = tid & 31;
    for (int s = w; s < S_; s += 16) {
        const float* pr = d_pre + (size_t)b * (S_ * U_) + (size_t)s * U_;
        float p = 0.f;
        for (int u = lane; u < U_; u += 32) p += tanhf(pr[u] + qs[u]) * Va[u];
#pragma unroll
        for (int o = 16; o > 0; o >>= 1) p += __shfl_xor_sync(0xffffffffu, p, o);
        if (lane == 0) sc[s] = p + bvp[0];
    }
    __syncthreads();

    if (tid < 32) {
        float v0 = sc[tid], v1 = sc[tid + 32];
        float m = fmaxf(v0, v1);
#pragma unroll
        for (int o = 16; o > 0; o >>= 1) m = fmaxf(m, __shfl_xor_sync(0xffffffffu, m, o));
        float e0 = expf(v0 - m), e1 = expf(v1 - m);
        float s = e0 + e1;
#pragma unroll
        for (int o = 16; o > 0; o >>= 1) s += __shfl_xor_sync(0xffffffffu, s, o);
        float inv = 1.f / s;
        sc[tid] = e0 * inv; sc[tid + 32] = e1 * inv;
    }
    __syncthreads();

    for (int u = tid; u < U_; u += 512) {
        float a = 0.f;
        const float* eb = d_enc + (size_t)b * (S_ * U_) + u;
#pragma unroll 8
        for (int s = 0; s < S_; s++) a += sc[s] * eb[(size_t)s * U_];
        d_xcat[(size_t)b * U_ + u] = a;
    }
}

// ---------------- argmax ----------------
__global__ void argmax_k(const float* __restrict__ logits, long long* outI, float* outF, int asFloat)
{
    const int row = blockIdx.x;
    const float* p = logits + (size_t)row * V_;
    const int tid = threadIdx.x;
    float best = -INFINITY; int bi = 0;
    for (int v = tid; v < V_; v += 256) {
        float val = p[v];
        if (val > best) { best = val; bi = v; }
    }
    __shared__ float bvs[256]; __shared__ int bis[256];
    bvs[tid] = best; bis[tid] = bi;
    __syncthreads();
    for (int st = 128; st > 0; st >>= 1) {
        if (tid < st) {
            float ov = bvs[tid + st]; int oi = bis[tid + st];
            if (ov > bvs[tid] || (ov == bvs[tid] && oi < bis[tid])) { bvs[tid] = ov; bis[tid] = oi; }
        }
        __syncthreads();
    }
    if (tid == 0) {
        if (asFloat) outF[row] = (float)bis[0];
        else         outI[row] = (long long)bis[0];
    }
}

// ---------------- launcher ----------------
static float* symaddr(const void* sym) {
    void* p = nullptr;
    cudaGetSymbolAddress(&p, sym);
    return (float*)p;
}

extern "C" void kernel_launch(void* const* d_in, const int* in_sizes, int n_in,
                              void* d_out, int out_size)
{
    static cudaStream_t s2 = nullptr;
    static cudaEvent_t ev[16];
    if (!s2) {
        cudaStreamCreateWithFlags(&s2, cudaStreamNonBlocking);
        for (int i = 0; i < 16; i++) cudaEventCreateWithFlags(&ev[i], cudaEventDisableTiming);
    }

    const int s0 = (n_in >= 22) ? 4 : 2;
    const int*   enc_in  = (const int*)d_in[0];
    const int*   teacher = (const int*)d_in[1];
    const float* Ee      = (const float*)d_in[s0 + 0];
    const float* eWx     = (const float*)d_in[s0 + 1];
    const float* eWh     = (const float*)d_in[s0 + 2];
    const float* eb_in   = (const float*)d_in[s0 + 3];
    const float* eb_rec  = (const float*)d_in[s0 + 4];
    const float* Ed      = (const float*)d_in[s0 + 5];
    const float* dWx     = (const float*)d_in[s0 + 6];
    const float* db_in   = (const float*)d_in[s0 + 8];
    const float* db_rec  = (const float*)d_in[s0 + 9];
    const float* W1      = (const float*)d_in[s0 + 10];
    const float* b1      = (const float*)d_in[s0 + 11];
    const float* W2      = (const float*)d_in[s0 + 12];
    const float* b2      = (const float*)d_in[s0 + 13];
    const float* Va      = (const float*)d_in[s0 + 14];
    const float* bvp     = (const float*)d_in[s0 + 15];
    const float* Wf      = (const float*)d_in[s0 + 16];
    const float* bf      = (const float*)d_in[s0 + 17];

    float* hbase = symaddr(d_hbuf);
    float* hdec  = symaddr(d_hdec);
    float* encp  = symaddr(d_enc);
    float* prep  = symaddr(d_pre);
    float* qp    = symaddr(d_q);
    float* gpart = symaddr(d_gpart);
    float* xcat  = symaddr(d_xcat);
    float* demb  = symaddr(d_demb);
    float* Hall  = symaddr(d_Hall);
    float* lalt  = symaddr(d_logits_alt);
    float* gxall = symaddr(d_gxall);
    float* WhP   = symaddr(d_WhP);
    float* dWxP  = symaddr(d_dWxP);
    unsigned int* ctr; { void* p; cudaGetSymbolAddress(&p, d_ctr); ctr = (unsigned int*)p; }
    __nv_bfloat16* WfT3;  { void* p; cudaGetSymbolAddress(&p, d_WfT3);  WfT3  = (__nv_bfloat16*)p; }
    __nv_bfloat16* W1T3;  { void* p; cudaGetSymbolAddress(&p, d_W1T3);  W1T3  = (__nv_bfloat16*)p; }
    __nv_bfloat16* eWxT3; { void* p; cudaGetSymbolAddress(&p, d_eWxT3); eWxT3 = (__nv_bfloat16*)p; }
    __nv_bfloat16* xembS; { void* p; cudaGetSymbolAddress(&p, d_xembS); xembS = (__nv_bfloat16*)p; }
    __nv_bfloat16* encS;  { void* p; cudaGetSymbolAddress(&p, d_encS);  encS  = (__nv_bfloat16*)p; }
    __nv_bfloat16* HallS; { void* p; cudaGetSymbolAddress(&p, d_HallS); HallS = (__nv_bfloat16*)p; }

    const long long LOGN = (long long)B_ * T_ * V_;
    float* logits_dst = (float*)d_out;
    long long* predI = nullptr; float* predF = nullptr; int asFloat = 0;
    if ((long long)out_size == LOGN + 512) { predF = (float*)d_out + LOGN; asFloat = 1; }
    else if ((long long)out_size == LOGN + 1024) { predI = (long long*)((float*)d_out + LOGN); }
    else if (out_size == 512) { logits_dst = lalt; predI = (long long*)d_out; }

    cudaMemsetAsync(hbase, 0, (size_t)B_ * U_ * sizeof(float));

    // main stream front: eWh perm, eWx split, embed, gx chunk0 (steps 0-15)
    perm3<<<U_ * G_ / 256, 256>>>(eWh, WhP);
    conv_splitB_v8<<<(E_ * (G_ / 8) + 255) / 256, 256>>>(eWx, eWxT3, E_, G_, G_);
    embed_split<<<2048, 256>>>(enc_in, Ee);
    gemm_bf16<0><<<dim3(G_ / 64, 4), 256>>>(xembS, eWxT3, eb_in, gxall, G_, G_, 768, G_, 0);

    // encoder steps 0 and 1
    for (int s = 0; s < 2; s++) {
        float* hin  = hbase + (size_t)(s & 1) * B_ * U_;
        float* hout = hbase + (size_t)((s + 1) & 1) * B_ * U_;
        step_gemm<48,3,8,1><<<dim3(G_ / 48, 1, 8), 128>>>(
            hin, WhP, gxall + (size_t)s * B_ * G_, eb_rec,
            hin, hout, encp + (size_t)s * U_, gpart, nullptr, ctr, G_, U_);
    }

    // fork side stream: gx chunks 1-3, W1 split, dWx perm, demb, Wf split
    cudaEventRecord(ev[0], 0);
    cudaStreamWaitEvent(s2, ev[0], 0);
    for (int c = 1; c < 4; c++) {
        gemm_bf16<0><<<dim3(G_ / 64, 4), 256, 0, s2>>>(
            xembS + (size_t)c * 512 * 768, eWxT3, eb_in,
            gxall + (size_t)c * 512 * G_, G_, G_, 768, G_, 0);
        cudaEventRecord(ev[c], s2);                 // gx chunk c ready
    }
    conv_splitB_v8<<<(U_ * (U_ / 8) + 255) / 256, 256, 0, s2>>>(W1, W1T3, U_, U_, U_);
    cudaEventRecord(ev[4], s2);                     // W1T3 ready
    perm3<<<(U_ + E_) * G_ / 256, 256, 0, s2>>>(dWx, dWxP);
    demb_gemm<<<dim3(G_ / 64, 16), 128, 0, s2>>>(Ed, teacher, dWxP, demb);
    cudaEventRecord(ev[5], s2);                     // dWxP + demb ready
    conv_splitB_v8<<<(U_ * (VP_ / 8) + 255) / 256, 256, 0, s2>>>(Wf, WfT3, U_, V_, VP_);

    // encoder steps 2..63 (wait for gx chunk c before step 16c)
    for (int s = 2; s < S_; s++) {
        if ((s & 15) == 0) cudaStreamWaitEvent(0, ev[s >> 4], 0);
        float* hin  = hbase + (size_t)(s & 1) * B_ * U_;
        float* hout = hbase + (size_t)((s + 1) & 1) * B_ * U_;
        step_gemm<48,3,8,1><<<dim3(G_ / 48, 1, 8), 128>>>(
            hin, WhP, gxall + (size_t)s * B_ * G_, eb_rec,
            hin, hout, encp + (size_t)s * U_, gpart, nullptr, ctr, G_, U_);
    }

    // pre_enc: bulk split of d_enc then GEMM (needs W1T3)
    conv_splitA<<<(B_ * S_ * U_) / 256, 256>>>(encp, encS);
    cudaStreamWaitEvent(0, ev[4], 0);
    gemm_bf16<0><<<dim3(U_ / 64, (B_ * S_) / 128), 256>>>(encS, W1T3, b1, prep, U_, U_, 3072, U_, 0);

    // decoder (needs dWxP + demb)
    cudaStreamWaitEvent(0, ev[5], 0);
    for (int t = 0; t < T_; t++) {
        const float* hd = (t == 0) ? hbase : hdec;
        step_gemm<64,4,8,0><<<dim3(U_ / 64, 1, 8), 128>>>(
            hd, W2, nullptr, b2, nullptr, nullptr, nullptr, gpart, qp, ctr + 64, U_, U_);
        attn_ctx<<<B_, 512>>>(Va, bvp);
        step_gemm<48,3,8,2><<<dim3(G_ / 48, 1, 8), 128>>>(
            xcat, dWxP, db_in, db_rec, demb + (size_t)t * 32 * G_, hdec,
            Hall + (size_t)t * B_ * U_, gpart, nullptr, ctr + 128, G_, U_);
        if ((t & 3) == 3) {
            int c = t >> 2;
            cudaEventRecord(ev[7 + c], 0);
            cudaStreamWaitEvent(s2, ev[7 + c], 0);
            conv_splitA<<<512, 256, 0, s2>>>(Hall + (size_t)c * 128 * U_,
                                             HallS + (size_t)c * 128 * 3072);
            gemm_bf16<1><<<dim3(VP_ / 64, 1), 256, 0, s2>>>(
                HallS + (size_t)c * 128 * 3072, WfT3, bf, logits_dst, 0, V_, 3072, VP_, c * 128);
        }
    }

    // join side stream, then argmax
    cudaEventRecord(ev[11], s2);
    cudaStreamWaitEvent(0, ev[11], 0);
    if (predI || predF) argmax_k<<<T_ * B_, 256>>>(logits_dst, predI, predF, asFloat);
}

// round 14
// speedup vs baseline: 1.0555x; 1.0390x over previous
#include <cuda_runtime.h>
#include <cuda_bf16.h>
#include <math.h>
#include <stdint.h>

#define B_ 32
#define S_ 64
#define T_ 16
#define U_ 1024
#define E_ 256
#define V_ 20200
#define G_ 3072
#define VP_ 20224

// ---------------- device scratch ----------------
__device__ __align__(16) float d_gxall[S_*B_*G_];
__device__ __align__(16) float d_hbuf[2][B_*U_];
__device__ __align__(16) float d_hdec[B_*U_];
__device__ __align__(16) float d_enc[B_*S_*U_];          // [b][s][u]
__device__ __align__(16) float d_pre[B_*S_*U_];          // rows b*64+s
__device__ __align__(16) float d_q[B_*U_];
__device__ __align__(16) float d_gpart[8][B_*G_];
__device__ __align__(16) float d_xcat[B_*U_];
__device__ __align__(16) float d_demb[512*G_];           // rows t*32+b
__device__ __align__(16) float d_Hall[T_*B_*U_];         // rows t*32+b
__device__ __align__(16) float d_logits_alt[T_*B_*V_];
__device__ __align__(16) float d_WhP[U_*G_];
__device__ __align__(16) float d_dWxP[(U_+E_)*G_];
__device__ __align__(16) __nv_bfloat16 d_WfT3[(size_t)3*1024*VP_];
__device__ __align__(16) __nv_bfloat16 d_W1T3[3*1024*1024];
__device__ __align__(16) __nv_bfloat16 d_eWxT3[3*256*G_];
__device__ __align__(16) __nv_bfloat16 d_xembS[2048*768];
__device__ __align__(16) __nv_bfloat16 d_encS[(size_t)2048*3072];   // rows b*64+s
__device__ __align__(16) __nv_bfloat16 d_HallS[512*3072];           // rows t*32+b
__device__ unsigned int d_ctr[3*64];

__device__ __forceinline__ float sigm(float x) { return 1.f / (1.f + expf(-x)); }

// ---------------- cp.async helpers ----------------
__device__ __forceinline__ void cp16(uint32_t dst, const void* src) {
    asm volatile("cp.async.cg.shared.global [%0], [%1], 16;" :: "r"(dst), "l"(src));
}
__device__ __forceinline__ void cp_commit() {
    asm volatile("cp.async.commit_group;");
}
template<int N>
__device__ __forceinline__ void cp_wait() {
    asm volatile("cp.async.wait_group %0;" :: "n"(N));
}

// ---------------- setup kernels ----------------
__global__ void perm3(const float* __restrict__ W, float* __restrict__ out) {
    int idx = blockIdx.x * 256 + threadIdx.x;
    int k = idx / G_, c = idx - k * G_;
    int u = c / 3, g = c - u * 3;
    out[idx] = W[(size_t)k * G_ + g * U_ + u];
}

__global__ void embed_split(const int* __restrict__ enc_in, const float* __restrict__ Ee) {
    int idx = blockIdx.x * 256 + threadIdx.x;
    int r = idx >> 8, e = idx & 255;
    int s = r >> 5, b = r & 31;
    float x = Ee[(size_t)enc_in[b * S_ + s] * E_ + e];
    __nv_bfloat16 hi = __float2bfloat16(x);
    __nv_bfloat16 lo = __float2bfloat16(x - __bfloat162float(hi));
    size_t base = (size_t)r * 768;
    d_xembS[base + e] = hi; d_xembS[base + 256 + e] = lo; d_xembS[base + 512 + e] = hi;
}

// A [M][1024] fp32 -> [M][3072] bf16 = [hi|lo|hi]
__global__ void conv_splitA(const float* __restrict__ A, __nv_bfloat16* __restrict__ out) {
    int idx = blockIdx.x * 256 + threadIdx.x;
    int m = idx >> 10, k = idx & 1023;
    float x = A[idx];
    __nv_bfloat16 hi = __float2bfloat16(x);
    __nv_bfloat16 lo = __float2bfloat16(x - __bfloat162float(hi));
    size_t base = (size_t)m * 3072;
    out[base + k] = hi; out[base + 1024 + k] = lo; out[base + 2048 + k] = hi;
}

__global__ void conv_splitB_v8(const float* __restrict__ W, __nv_bfloat16* __restrict__ out,
                               int K, int N, int NP) {
    int idx = blockIdx.x * 256 + threadIdx.x;
    int per = NP >> 3;
    int k = idx / per, n = (idx - k * per) * 8;
    if (k >= K) return;
    float v[8];
    if (n + 8 <= N) {
        float4 a = *(const float4*)&W[(size_t)k * N + n];
        float4 b = *(const float4*)&W[(size_t)k * N + n + 4];
        v[0]=a.x; v[1]=a.y; v[2]=a.z; v[3]=a.w; v[4]=b.x; v[5]=b.y; v[6]=b.z; v[7]=b.w;
    } else {
#pragma unroll
        for (int j = 0; j < 8; j++) v[j] = (n + j < N) ? W[(size_t)k * N + n + j] : 0.f;
    }
    __nv_bfloat16 hi[8], lo[8];
#pragma unroll
    for (int j = 0; j < 8; j++) {
        hi[j] = __float2bfloat16(v[j]);
        lo[j] = __float2bfloat16(v[j] - __bfloat162float(hi[j]));
    }
    size_t p = (size_t)k * NP + n, sK = (size_t)K * NP;
    *(uint4*)&out[p]          = *(uint4*)hi;
    *(uint4*)&out[sK + p]     = *(uint4*)hi;
    *(uint4*)&out[2 * sK + p] = *(uint4*)lo;
}

// demb[t*32+b][c] = Ed[teacher[b][t]] @ dWxP[1024:1280][c]
__global__ __launch_bounds__(128) void demb_gemm(
    const float* __restrict__ Ed, const int* __restrict__ teacher,
    const float* __restrict__ dWxP, float* __restrict__ demb)
{
    __shared__ float As[16][32];
    __shared__ float Bs[16][64];
    const int tid = threadIdx.x;
    const int tx = tid & 15, ty = tid >> 4;
    const int n0 = blockIdx.x * 64;
    const int m0 = blockIdx.y * 32;
    float acc[4][4] = {};
    for (int kt = 0; kt < 16; kt++) {
#pragma unroll
        for (int ii = tid; ii < 512; ii += 128) {
            int k = ii & 15, m = ii >> 4;
            int gr = m0 + m, t = gr >> 5, b = gr & 31;
            As[k][m] = Ed[(size_t)teacher[b * T_ + t] * E_ + kt * 16 + k];
        }
#pragma unroll
        for (int ii = tid; ii < 1024; ii += 128) {
            int k = ii >> 6, n = ii & 63;
            Bs[k][n] = dWxP[(size_t)(1024 + kt * 16 + k) * G_ + n0 + n];
        }
        __syncthreads();
#pragma unroll
        for (int kk = 0; kk < 16; kk++) {
            float4 av = *(const float4*)&As[kk][ty * 4];
            float a[4] = {av.x, av.y, av.z, av.w};
#pragma unroll
            for (int j = 0; j < 4; j++) {
                float bv = Bs[kk][tx * 4 + j];
#pragma unroll
                for (int i = 0; i < 4; i++) acc[i][j] += a[i] * bv;
            }
        }
        __syncthreads();
    }
#pragma unroll
    for (int i = 0; i < 4; i++)
#pragma unroll
        for (int j = 0; j < 4; j++)
            demb[(size_t)(m0 + ty * 4 + i) * G_ + n0 + tx * 4 + j] = acc[i][j];
}

// ---------------- tensor-core bf16 GEMM (3-stage cp.async pipeline) ----------------
__device__ __forceinline__ void mma_bf16(float* c, const uint32_t* a, const uint32_t* b) {
    asm volatile("mma.sync.aligned.m16n8k16.row.col.f32.bf16.bf16.f32 "
        "{%0,%1,%2,%3},{%4,%5,%6,%7},{%8,%9},{%0,%1,%2,%3};"
        : "+f"(c[0]), "+f"(c[1]), "+f"(c[2]), "+f"(c[3])
        : "r"(a[0]), "r"(a[1]), "r"(a[2]), "r"(a[3]), "r"(b[0]), "r"(b[1]));
}
__device__ __forceinline__ void ldsm_x4(uint32_t* r, uint32_t addr) {
    asm volatile("ldmatrix.sync.aligned.m8n8.x4.shared.b16 {%0,%1,%2,%3}, [%4];"
        : "=r"(r[0]), "=r"(r[1]), "=r"(r[2]), "=r"(r[3]) : "r"(addr));
}
__device__ __forceinline__ void ldsm_x2_trans(uint32_t* r, uint32_t addr) {
    asm volatile("ldmatrix.sync.aligned.m8n8.x2.trans.shared.b16 {%0,%1}, [%2];"
        : "=r"(r[0]), "=r"(r[1]) : "r"(addr));
}

// MODE 0: C[gm*ldC+gc]; MODE 1: logits scatter gg=mofs+gm=t*32+b -> row b*16+t
template<int MODE>
__global__ __launch_bounds__(256) void gemm_bf16(
    const __nv_bfloat16* __restrict__ A, const __nv_bfloat16* __restrict__ Bkm,
    const float* __restrict__ bias, float* __restrict__ C,
    int ldC, int Nreal, int K3, int ldB, int mofs)
{
    __shared__ __nv_bfloat16 As[3][128 * 40];
    __shared__ __nv_bfloat16 Bs[3][32 * 72];
    const int tid = threadIdx.x;
    const int wid = tid >> 5, lane = tid & 31;
    const int gid = lane >> 2, tig = lane & 3;
    const int wm = wid & 3, wn = wid >> 2;
    const int m0 = blockIdx.y * 128, n0 = blockIdx.x * 64;

    const uint32_t asBase = (uint32_t)__cvta_generic_to_shared(&As[0][0]);
    const uint32_t bsBase = (uint32_t)__cvta_generic_to_shared(&Bs[0][0]);
    const int lquad = lane >> 3, l7 = lane & 7, l15 = lane & 15;
    const uint32_t aLane = (uint32_t)((((lquad & 1) * 8 + l7) * 80) + (lquad >> 1) * 16);

    float acc[2][4][4] = {};
    const int nkt = K3 >> 5;

    const int rowA0 = tid >> 2,          cA0 = tid & 3;
    const int rowA1 = (tid + 256) >> 2;
    const int rB = tid >> 3,             cB = tid & 7;
    const int ga0 = m0 + rowA0, ga1 = m0 + rowA1;

    const uint32_t dA0 = asBase + (uint32_t)((rowA0 * 40 + cA0 * 8) * 2);
    const uint32_t dA1 = asBase + (uint32_t)((rowA1 * 40 + cA0 * 8) * 2);
    const uint32_t dB  = bsBase + (uint32_t)((rB * 72 + cB * 8) * 2);
    const uint32_t stA = 128 * 40 * 2, stB = 32 * 72 * 2;

    auto issue = [&](int kt, int buf) {
        cp16(dA0 + buf * stA, &A[(size_t)ga0 * K3 + kt * 32 + cA0 * 8]);
        cp16(dA1 + buf * stA, &A[(size_t)ga1 * K3 + kt * 32 + cA0 * 8]);
        cp16(dB  + buf * stB, &Bkm[(size_t)(kt * 32 + rB) * ldB + n0 + cB * 8]);
    };

    issue(0, 0); cp_commit();
    if (nkt > 1) issue(1, 1);
    cp_commit();

    for (int kt = 0; kt < nkt; kt++) {
        const int buf = kt % 3;
        if (kt + 2 < nkt) issue(kt + 2, (kt + 2) % 3);
        cp_commit();
        cp_wait<2>();
        __syncthreads();
#pragma unroll
        for (int ks = 0; ks < 2; ks++) {
            uint32_t a[2][4], b[4][2];
#pragma unroll
            for (int mi = 0; mi < 2; mi++)
                ldsm_x4(a[mi], asBase + (uint32_t)(buf * stA) +
                               (uint32_t)((wm * 32 + mi * 16) * 80 + ks * 32) + aLane);
#pragma unroll
            for (int ni = 0; ni < 4; ni++)
                ldsm_x2_trans(b[ni], bsBase + (uint32_t)(buf * stB) +
                              (uint32_t)(((ks * 16 + l15) * 72 + (wn * 32 + ni * 8)) * 2));
#pragma unroll
            for (int mi = 0; mi < 2; mi++)
#pragma unroll
                for (int ni = 0; ni < 4; ni++)
                    mma_bf16(acc[mi][ni], a[mi], b[ni]);
        }
        __syncthreads();
    }

#pragma unroll
    for (int mi = 0; mi < 2; mi++)
#pragma unroll
        for (int ni = 0; ni < 4; ni++) {
            int gm0 = m0 + wm * 32 + mi * 16 + gid;
            int gc0 = n0 + wn * 32 + ni * 8 + tig * 2;
#pragma unroll
            for (int e = 0; e < 4; e++) {
                int gm = gm0 + (e >> 1) * 8;
                int gc = gc0 + (e & 1);
                float v = acc[mi][ni][e];
                if (MODE == 1) {
                    if (gc < Nreal) {
                        int gg = mofs + gm;
                        int bb = gg & 31, tt = gg >> 5;
                        C[(size_t)(bb * T_ + tt) * Nreal + gc] = v + bias[gc];
                    }
                } else {
                    C[(size_t)gm * ldC + gc] = v + bias[gc];
                }
            }
        }
}

// ---------------- fused recurrence step ----------------
template<int BN, int TN, int NKC, int GATE>
__global__ __launch_bounds__(128) void step_gemm(
    const float* __restrict__ A, const float* __restrict__ Bm,
    const float* __restrict__ xb, const float* __restrict__ hb,
    const float* __restrict__ hin, float* __restrict__ hout,
    float* __restrict__ extra, float* __restrict__ part,
    float* __restrict__ qout, unsigned int* __restrict__ ctr,
    int N, int K)
{
    constexpr int PB = (16 * BN) / 128;
    __shared__ float As[16][32];
    __shared__ float Bs[16][BN];
    __shared__ int doneflag;
    const int tid = threadIdx.x;
    const int tx = tid & 15, ty = tid >> 4;
    const int n0 = blockIdx.x * BN;
    const int z = blockIdx.z;
    const int k0 = z * NKC * 16;

    float pa[4], pb[PB];
    auto ldA = [&](int kt) {
#pragma unroll
        for (int i = 0; i < 4; i++) {
            int ii = tid + i * 128, k = ii & 15, m = ii >> 4;
            pa[i] = A[(size_t)m * K + k0 + kt * 16 + k];
        }
    };
    auto ldB = [&](int kt) {
#pragma unroll
        for (int i = 0; i < PB; i++) {
            int ii = tid + i * 128, k = ii / BN, n = ii - k * BN;
            pb[i] = Bm[(size_t)(k0 + kt * 16 + k) * N + n0 + n];
        }
    };

    float acc[4][TN];
#pragma unroll
    for (int i = 0; i < 4; i++)
#pragma unroll
        for (int j = 0; j < TN; j++) acc[i][j] = 0.f;

    ldA(0); ldB(0);
    for (int kt = 0; kt < NKC; kt++) {
#pragma unroll
        for (int i = 0; i < 4; i++) {
            int ii = tid + i * 128;
            As[ii & 15][ii >> 4] = pa[i];
        }
#pragma unroll
        for (int i = 0; i < PB; i++) {
            int ii = tid + i * 128, k = ii / BN;
            Bs[k][ii - k * BN] = pb[i];
        }
        __syncthreads();
        if (kt + 1 < NKC) { ldA(kt + 1); ldB(kt + 1); }
#pragma unroll
        for (int kk = 0; kk < 16; kk++) {
            float4 av = *reinterpret_cast<const float4*>(&As[kk][ty * 4]);
            float a[4] = {av.x, av.y, av.z, av.w};
#pragma unroll
            for (int j = 0; j < TN; j++) {
                float bv = Bs[kk][tx * TN + j];
#pragma unroll
                for (int i = 0; i < 4; i++) acc[i][j] += a[i] * bv;
            }
        }
        __syncthreads();
    }
#pragma unroll
    for (int i = 0; i < 4; i++) {
        int gm = ty * 4 + i;
#pragma unroll
        for (int j = 0; j < TN; j++)
            part[((size_t)(z * 32 + gm)) * N + n0 + tx * TN + j] = acc[i][j];
    }
    __threadfence();
    __syncthreads();
    if (tid == 0) {
        unsigned int prev = atomicAdd(&ctr[blockIdx.x], 1u);
        doneflag = (prev == 7u);
        if (prev == 7u) ctr[blockIdx.x] = 0u;
    }
    __syncthreads();
    if (!doneflag) return;
    __threadfence();

    if (GATE == 0) {
#pragma unroll
        for (int i = 0; i < 16; i++) {
            int idx = tid + i * 128;
            int b = idx & 31, nl = idx >> 5;
            int n = n0 + nl;
            float s = 0.f;
#pragma unroll
            for (int zz = 0; zz < 8; zz++) s += part[((size_t)(zz * 32 + b)) * N + n];
            qout[b * U_ + n] = s + hb[n];
        }
    } else {
        const int u0 = n0 / 3;
#pragma unroll
        for (int i = 0; i < 4; i++) {
            int idx = tid + i * 128;
            int b = idx & 31, ul = idx >> 5;
            int u = u0 + ul;
            float g[3];
#pragma unroll
            for (int gg = 0; gg < 3; gg++) {
                float s = 0.f;
#pragma unroll
                for (int zz = 0; zz < 8; zz++)
                    s += part[((size_t)(zz * 32 + b)) * N + n0 + ul * 3 + gg];
                g[gg] = s;
            }
            float h;
            if (GATE == 1) {
                const float* gx = xb + (size_t)b * G_;
                float zg = sigm(gx[u] + g[0] + hb[u]);
                float rg = sigm(gx[U_ + u] + g[1] + hb[U_ + u]);
                float cg = tanhf(gx[2 * U_ + u] + rg * (g[2] + hb[2 * U_ + u]));
                h = zg * hin[b * U_ + u] + (1.f - zg) * cg;
                hout[b * U_ + u] = h;
                extra[(size_t)b * (S_ * U_) + u] = h;
            } else {
                const float* de = hin + (size_t)b * G_ + n0 + ul * 3;
                float zg = sigm(g[0] + de[0] + xb[u] + hb[u]);
                float rg = sigm(g[1] + de[1] + xb[U_ + u] + hb[U_ + u]);
                float cg = tanhf(g[2] + de[2] + xb[2 * U_ + u] + rg * hb[2 * U_ + u]);
                h = (1.f - zg) * cg;
                hout[b * U_ + u] = h;
                extra[(size_t)b * U_ + u] = h;
            }
        }
    }
}

// ---------------- attention + context ----------------
__global__ void attn_ctx(const float* __restrict__ Va, const float* __restrict__ bvp)
{
    const int b = blockIdx.x, tid = threadIdx.x;
    __shared__ float qs[U_];
    __shared__ float sc[S_];

    for (int u = tid; u < U_; u += 512) qs[u] = d_q[b * U_ + u];
    __syncthreads();

    const int w = tid >> 5, lane = tid & 31;
    for (int s = w; s < S_; s += 16) {
        const float* pr = d_pre + (size_t)b * (S_ * U_) + (size_t)s * U_;
        float p = 0.f;
        for (int u = lane; u < U_; u += 32) p += tanhf(pr[u] + qs[u]) * Va[u];
#pragma unroll
        for (int o = 16; o > 0; o >>= 1) p += __shfl_xor_sync(0xffffffffu, p, o);
        if (lane == 0) sc[s] = p + bvp[0];
    }
    __syncthreads();

    if (tid < 32) {
        float v0 = sc[tid], v1 = sc[tid + 32];
        float m = fmaxf(v0, v1);
#pragma unroll
        for (int o = 16; o > 0; o >>= 1) m = fmaxf(m, __shfl_xor_sync(0xffffffffu, m, o));
        float e0 = expf(v0 - m), e1 = expf(v1 - m);
        float s = e0 + e1;
#pragma unroll
        for (int o = 16; o > 0; o >>= 1) s += __shfl_xor_sync(0xffffffffu, s, o);
        float inv = 1.f / s;
        sc[tid] = e0 * inv; sc[tid + 32] = e1 * inv;
    }
    __syncthreads();

    for (int u = tid; u < U_; u += 512) {
        float a = 0.f;
        const float* eb = d_enc + (size_t)b * (S_ * U_) + u;
#pragma unroll 8
        for (int s = 0; s < S_; s++) a += sc[s] * eb[(size_t)s * U_];
        d_xcat[(size_t)b * U_ + u] = a;
    }
}

// ---------------- argmax ----------------
__global__ void argmax_k(const float* __restrict__ logits, long long* outI, float* outF, int asFloat)
{
    const int row = blockIdx.x;
    const float* p = logits + (size_t)row * V_;
    const int tid = threadIdx.x;
    float best = -INFINITY; int bi = 0;
    for (int v = tid; v < V_; v += 256) {
        float val = p[v];
        if (val > best) { best = val; bi = v; }
    }
    __shared__ float bvs[256]; __shared__ int bis[256];
    bvs[tid] = best; bis[tid] = bi;
    __syncthreads();
    for (int st = 128; st > 0; st >>= 1) {
        if (tid < st) {
            float ov = bvs[tid + st]; int oi = bis[tid + st];
            if (ov > bvs[tid] || (ov == bvs[tid] && oi < bis[tid])) { bvs[tid] = ov; bis[tid] = oi; }
        }
        __syncthreads();
    }
    if (tid == 0) {
        if (asFloat) outF[row] = (float)bis[0];
        else         outI[row] = (long long)bis[0];
    }
}

// ---------------- launcher ----------------
static float* symaddr(const void* sym) {
    void* p = nullptr;
    cudaGetSymbolAddress(&p, sym);
    return (float*)p;
}

extern "C" void kernel_launch(void* const* d_in, const int* in_sizes, int n_in,
                              void* d_out, int out_size)
{
    static cudaStream_t s2 = nullptr;
    static cudaEvent_t ev[16];
    if (!s2) {
        cudaStreamCreateWithFlags(&s2, cudaStreamNonBlocking);
        for (int i = 0; i < 16; i++) cudaEventCreateWithFlags(&ev[i], cudaEventDisableTiming);
    }

    const int s0 = (n_in >= 22) ? 4 : 2;
    const int*   enc_in  = (const int*)d_in[0];
    const int*   teacher = (const int*)d_in[1];
    const float* Ee      = (const float*)d_in[s0 + 0];
    const float* eWx     = (const float*)d_in[s0 + 1];
    const float* eWh     = (const float*)d_in[s0 + 2];
    const float* eb_in   = (const float*)d_in[s0 + 3];
    const float* eb_rec  = (const float*)d_in[s0 + 4];
    const float* Ed      = (const float*)d_in[s0 + 5];
    const float* dWx     = (const float*)d_in[s0 + 6];
    const float* db_in   = (const float*)d_in[s0 + 8];
    const float* db_rec  = (const float*)d_in[s0 + 9];
    const float* W1      = (const float*)d_in[s0 + 10];
    const float* b1      = (const float*)d_in[s0 + 11];
    const float* W2      = (const float*)d_in[s0 + 12];
    const float* b2      = (const float*)d_in[s0 + 13];
    const float* Va      = (const float*)d_in[s0 + 14];
    const float* bvp     = (const float*)d_in[s0 + 15];
    const float* Wf      = (const float*)d_in[s0 + 16];
    const float* bf      = (const float*)d_in[s0 + 17];

    float* hbase = symaddr(d_hbuf);
    float* hdec  = symaddr(d_hdec);
    float* encp  = symaddr(d_enc);
    float* prep  = symaddr(d_pre);
    float* qp    = symaddr(d_q);
    float* gpart = symaddr(d_gpart);
    float* xcat  = symaddr(d_xcat);
    float* demb  = symaddr(d_demb);
    float* Hall  = symaddr(d_Hall);
    float* lalt  = symaddr(d_logits_alt);
    float* gxall = symaddr(d_gxall);
    float* WhP   = symaddr(d_WhP);
    float* dWxP  = symaddr(d_dWxP);
    unsigned int* ctr; { void* p; cudaGetSymbolAddress(&p, d_ctr); ctr = (unsigned int*)p; }
    __nv_bfloat16* WfT3;  { void* p; cudaGetSymbolAddress(&p, d_WfT3);  WfT3  = (__nv_bfloat16*)p; }
    __nv_bfloat16* W1T3;  { void* p; cudaGetSymbolAddress(&p, d_W1T3);  W1T3  = (__nv_bfloat16*)p; }
    __nv_bfloat16* eWxT3; { void* p; cudaGetSymbolAddress(&p, d_eWxT3); eWxT3 = (__nv_bfloat16*)p; }
    __nv_bfloat16* xembS; { void* p; cudaGetSymbolAddress(&p, d_xembS); xembS = (__nv_bfloat16*)p; }
    __nv_bfloat16* encS;  { void* p; cudaGetSymbolAddress(&p, d_encS);  encS  = (__nv_bfloat16*)p; }
    __nv_bfloat16* HallS; { void* p; cudaGetSymbolAddress(&p, d_HallS); HallS = (__nv_bfloat16*)p; }

    const long long LOGN = (long long)B_ * T_ * V_;
    float* logits_dst = (float*)d_out;
    long long* predI = nullptr; float* predF = nullptr; int asFloat = 0;
    if ((long long)out_size == LOGN + 512) { predF = (float*)d_out + LOGN; asFloat = 1; }
    else if ((long long)out_size == LOGN + 1024) { predI = (long long*)((float*)d_out + LOGN); }
    else if (out_size == 512) { logits_dst = lalt; predI = (long long*)d_out; }

    cudaMemsetAsync(hbase, 0, (size_t)B_ * U_ * sizeof(float));

    // main stream front: eWh perm, eWx split, embed, gx chunk0 (steps 0-15)
    perm3<<<U_ * G_ / 256, 256>>>(eWh, WhP);
    conv_splitB_v8<<<(E_ * (G_ / 8) + 255) / 256, 256>>>(eWx, eWxT3, E_, G_, G_);
    embed_split<<<2048, 256>>>(enc_in, Ee);
    gemm_bf16<0><<<dim3(G_ / 64, 4), 256>>>(xembS, eWxT3, eb_in, gxall, G_, G_, 768, G_, 0);

    // encoder steps 0 and 1
    for (int s = 0; s < 2; s++) {
        float* hin  = hbase + (size_t)(s & 1) * B_ * U_;
        float* hout = hbase + (size_t)((s + 1) & 1) * B_ * U_;
        step_gemm<48,3,8,1><<<dim3(G_ / 48, 1, 8), 128>>>(
            hin, WhP, gxall + (size_t)s * B_ * G_, eb_rec,
            hin, hout, encp + (size_t)s * U_, gpart, nullptr, ctr, G_, U_);
    }

    // fork side stream: gx chunks 1-3, W1 split, dWx perm, demb, Wf split
    cudaEventRecord(ev[0], 0);
    cudaStreamWaitEvent(s2, ev[0], 0);
    for (int c = 1; c < 4; c++) {
        gemm_bf16<0><<<dim3(G_ / 64, 4), 256, 0, s2>>>(
            xembS + (size_t)c * 512 * 768, eWxT3, eb_in,
            gxall + (size_t)c * 512 * G_, G_, G_, 768, G_, 0);
        cudaEventRecord(ev[c], s2);                 // gx chunk c ready
    }
    conv_splitB_v8<<<(U_ * (U_ / 8) + 255) / 256, 256, 0, s2>>>(W1, W1T3, U_, U_, U_);
    cudaEventRecord(ev[4], s2);                     // W1T3 ready
    perm3<<<(U_ + E_) * G_ / 256, 256, 0, s2>>>(dWx, dWxP);
    demb_gemm<<<dim3(G_ / 64, 16), 128, 0, s2>>>(Ed, teacher, dWxP, demb);
    cudaEventRecord(ev[5], s2);                     // dWxP + demb ready
    conv_splitB_v8<<<(U_ * (VP_ / 8) + 255) / 256, 256, 0, s2>>>(Wf, WfT3, U_, V_, VP_);

    // encoder steps 2..63 (wait for gx chunk c before step 16c)
    for (int s = 2; s < S_; s++) {
        if ((s & 15) == 0) cudaStreamWaitEvent(0, ev[s >> 4], 0);
        float* hin  = hbase + (size_t)(s & 1) * B_ * U_;
        float* hout = hbase + (size_t)((s + 1) & 1) * B_ * U_;
        step_gemm<48,3,8,1><<<dim3(G_ / 48, 1, 8), 128>>>(
            hin, WhP, gxall + (size_t)s * B_ * G_, eb_rec,
            hin, hout, encp + (size_t)s * U_, gpart, nullptr, ctr, G_, U_);
    }

    // pre_enc: bulk split of d_enc then GEMM (needs W1T3)
    conv_splitA<<<(B_ * S_ * U_) / 256, 256>>>(encp, encS);
    cudaStreamWaitEvent(0, ev[4], 0);
    gemm_bf16<0><<<dim3(U_ / 64, (B_ * S_) / 128), 256>>>(encS, W1T3, b1, prep, U_, U_, 3072, U_, 0);

    // decoder (needs dWxP + demb)
    cudaStreamWaitEvent(0, ev[5], 0);
    for (int t = 0; t < T_; t++) {
        const float* hd = (t == 0) ? hbase : hdec;
        step_gemm<64,4,8,0><<<dim3(U_ / 64, 1, 8), 128>>>(
            hd, W2, nullptr, b2, nullptr, nullptr, nullptr, gpart, qp, ctr + 64, U_, U_);
        attn_ctx<<<B_, 512>>>(Va, bvp);
        step_gemm<48,3,8,2><<<dim3(G_ / 48, 1, 8), 128>>>(
            xcat, dWxP, db_in, db_rec, demb + (size_t)t * 32 * G_, hdec,
            Hall + (size_t)t * B_ * U_, gpart, nullptr, ctr + 128, G_, U_);
        if ((t & 3) == 3) {
            int c = t >> 2;
            cudaEventRecord(ev[7 + c], 0);
            cudaStreamWaitEvent(s2, ev[7 + c], 0);
            conv_splitA<<<512, 256, 0, s2>>>(Hall + (size_t)c * 128 * U_,
                                             HallS + (size_t)c * 128 * 3072);
            gemm_bf16<1><<<dim3(VP_ / 64, 1), 256, 0, s2>>>(
                HallS + (size_t)c * 128 * 3072, WfT3, bf, logits_dst, 0, V_, 3072, VP_, c * 128);
        }
    }

    // join side stream, then argmax
    cudaEventRecord(ev[11], s2);
    cudaStreamWaitEvent(0, ev[11], 0);
    if (predI || predF) argmax_k<<<T_ * B_, 256>>>(logits_dst, predI, predF, asFloat);
}

// round 15
// speedup vs baseline: 1.1995x; 1.1364x over previous
#include <cuda_runtime.h>
#include <cuda_bf16.h>
#include <math.h>
#include <stdint.h>

#define B_ 32
#define S_ 64
#define T_ 16
#define U_ 1024
#define E_ 256
#define V_ 20200
#define G_ 3072
#define VP_ 20224

// ---------------- device scratch ----------------
__device__ __align__(16) float d_gxall[S_*B_*G_];
__device__ __align__(16) float d_hbuf[2][B_*U_];
__device__ __align__(16) float d_hdec[B_*U_];
__device__ __align__(16) float d_enc[B_*S_*U_];          // [b][s][u]
__device__ __align__(16) float d_pre[B_*S_*U_];          // rows b*64+s
__device__ __align__(16) float d_q[B_*U_];
__device__ __align__(16) float d_gpart[8][B_*G_];
__device__ __align__(16) float d_xcat[B_*U_];
__device__ __align__(16) float d_demb[512*G_];           // rows t*32+b
__device__ __align__(16) float d_Hall[T_*B_*U_];         // rows t*32+b
__device__ __align__(16) float d_logits_alt[T_*B_*V_];
__device__ __align__(16) float d_WhP[U_*G_];
__device__ __align__(16) float d_dWxP[(U_+E_)*G_];
__device__ __align__(16) __nv_bfloat16 d_WfT3[(size_t)3*1024*VP_];
__device__ __align__(16) __nv_bfloat16 d_W1T3[3*1024*1024];
__device__ __align__(16) __nv_bfloat16 d_eWxT3[3*256*G_];
__device__ __align__(16) __nv_bfloat16 d_xembS[2048*768];
__device__ __align__(16) __nv_bfloat16 d_encS[(size_t)2048*3072];   // rows b*64+s
__device__ __align__(16) __nv_bfloat16 d_HallS[512*3072];           // rows t*32+b
__device__ unsigned int d_ctr[3*64];

__device__ __forceinline__ float sigm(float x) { return 1.f / (1.f + expf(-x)); }

// ---------------- cp.async helpers ----------------
__device__ __forceinline__ void cp16(uint32_t dst, const void* src) {
    asm volatile("cp.async.cg.shared.global [%0], [%1], 16;" :: "r"(dst), "l"(src));
}
__device__ __forceinline__ void cp_commit() {
    asm volatile("cp.async.commit_group;");
}
template<int N>
__device__ __forceinline__ void cp_wait() {
    asm volatile("cp.async.wait_group %0;" :: "n"(N));
}

// ---------------- setup kernels ----------------
__global__ void perm3(const float* __restrict__ W, float* __restrict__ out) {
    int idx = blockIdx.x * 256 + threadIdx.x;
    int k = idx / G_, c = idx - k * G_;
    int u = c / 3, g = c - u * 3;
    out[idx] = W[(size_t)k * G_ + g * U_ + u];
}

__global__ void embed_split(const int* __restrict__ enc_in, const float* __restrict__ Ee) {
    int idx = blockIdx.x * 256 + threadIdx.x;
    int r = idx >> 8, e = idx & 255;
    int s = r >> 5, b = r & 31;
    float x = Ee[(size_t)enc_in[b * S_ + s] * E_ + e];
    __nv_bfloat16 hi = __float2bfloat16(x);
    __nv_bfloat16 lo = __float2bfloat16(x - __bfloat162float(hi));
    size_t base = (size_t)r * 768;
    d_xembS[base + e] = hi; d_xembS[base + 256 + e] = lo; d_xembS[base + 512 + e] = hi;
}

// A [M][1024] fp32 -> [M][3072] bf16 = [hi|lo|hi]
__global__ void conv_splitA(const float* __restrict__ A, __nv_bfloat16* __restrict__ out) {
    int idx = blockIdx.x * 256 + threadIdx.x;
    int m = idx >> 10, k = idx & 1023;
    float x = A[idx];
    __nv_bfloat16 hi = __float2bfloat16(x);
    __nv_bfloat16 lo = __float2bfloat16(x - __bfloat162float(hi));
    size_t base = (size_t)m * 3072;
    out[base + k] = hi; out[base + 1024 + k] = lo; out[base + 2048 + k] = hi;
}

__global__ void conv_splitB_v8(const float* __restrict__ W, __nv_bfloat16* __restrict__ out,
                               int K, int N, int NP) {
    int idx = blockIdx.x * 256 + threadIdx.x;
    int per = NP >> 3;
    int k = idx / per, n = (idx - k * per) * 8;
    if (k >= K) return;
    float v[8];
    if (n + 8 <= N) {
        float4 a = *(const float4*)&W[(size_t)k * N + n];
        float4 b = *(const float4*)&W[(size_t)k * N + n + 4];
        v[0]=a.x; v[1]=a.y; v[2]=a.z; v[3]=a.w; v[4]=b.x; v[5]=b.y; v[6]=b.z; v[7]=b.w;
    } else {
#pragma unroll
        for (int j = 0; j < 8; j++) v[j] = (n + j < N) ? W[(size_t)k * N + n + j] : 0.f;
    }
    __nv_bfloat16 hi[8], lo[8];
#pragma unroll
    for (int j = 0; j < 8; j++) {
        hi[j] = __float2bfloat16(v[j]);
        lo[j] = __float2bfloat16(v[j] - __bfloat162float(hi[j]));
    }
    size_t p = (size_t)k * NP + n, sK = (size_t)K * NP;
    *(uint4*)&out[p]          = *(uint4*)hi;
    *(uint4*)&out[sK + p]     = *(uint4*)hi;
    *(uint4*)&out[2 * sK + p] = *(uint4*)lo;
}

// demb[t*32+b][c] = Ed[teacher[b][t]] @ dWxP[1024:1280][c]
__global__ __launch_bounds__(128) void demb_gemm(
    const float* __restrict__ Ed, const int* __restrict__ teacher,
    const float* __restrict__ dWxP, float* __restrict__ demb)
{
    __shared__ float As[16][32];
    __shared__ float Bs[16][64];
    const int tid = threadIdx.x;
    const int tx = tid & 15, ty = tid >> 4;
    const int n0 = blockIdx.x * 64;
    const int m0 = blockIdx.y * 32;
    float acc[4][4] = {};
    for (int kt = 0; kt < 16; kt++) {
#pragma unroll
        for (int ii = tid; ii < 512; ii += 128) {
            int k = ii & 15, m = ii >> 4;
            int gr = m0 + m, t = gr >> 5, b = gr & 31;
            As[k][m] = Ed[(size_t)teacher[b * T_ + t] * E_ + kt * 16 + k];
        }
#pragma unroll
        for (int ii = tid; ii < 1024; ii += 128) {
            int k = ii >> 6, n = ii & 63;
            Bs[k][n] = dWxP[(size_t)(1024 + kt * 16 + k) * G_ + n0 + n];
        }
        __syncthreads();
#pragma unroll
        for (int kk = 0; kk < 16; kk++) {
            float4 av = *(const float4*)&As[kk][ty * 4];
            float a[4] = {av.x, av.y, av.z, av.w};
#pragma unroll
            for (int j = 0; j < 4; j++) {
                float bv = Bs[kk][tx * 4 + j];
#pragma unroll
                for (int i = 0; i < 4; i++) acc[i][j] += a[i] * bv;
            }
        }
        __syncthreads();
    }
#pragma unroll
    for (int i = 0; i < 4; i++)
#pragma unroll
        for (int j = 0; j < 4; j++)
            demb[(size_t)(m0 + ty * 4 + i) * G_ + n0 + tx * 4 + j] = acc[i][j];
}

// ---------------- tensor-core bf16 GEMM (3-stage cp.async pipeline) ----------------
__device__ __forceinline__ void mma_bf16(float* c, const uint32_t* a, const uint32_t* b) {
    asm volatile("mma.sync.aligned.m16n8k16.row.col.f32.bf16.bf16.f32 "
        "{%0,%1,%2,%3},{%4,%5,%6,%7},{%8,%9},{%0,%1,%2,%3};"
        : "+f"(c[0]), "+f"(c[1]), "+f"(c[2]), "+f"(c[3])
        : "r"(a[0]), "r"(a[1]), "r"(a[2]), "r"(a[3]), "r"(b[0]), "r"(b[1]));
}
__device__ __forceinline__ void ldsm_x4(uint32_t* r, uint32_t addr) {
    asm volatile("ldmatrix.sync.aligned.m8n8.x4.shared.b16 {%0,%1,%2,%3}, [%4];"
        : "=r"(r[0]), "=r"(r[1]), "=r"(r[2]), "=r"(r[3]) : "r"(addr));
}
__device__ __forceinline__ void ldsm_x2_trans(uint32_t* r, uint32_t addr) {
    asm volatile("ldmatrix.sync.aligned.m8n8.x2.trans.shared.b16 {%0,%1}, [%2];"
        : "=r"(r[0]), "=r"(r[1]) : "r"(addr));
}

// MODE 0: C[gm*ldC+gc]; MODE 1: logits scatter gg=mofs+gm=t*32+b -> row b*16+t,
//         with column offset nofs passed via ldC (n0 = blockIdx.x*64 + ldC)
template<int MODE>
__global__ __launch_bounds__(256) void gemm_bf16(
    const __nv_bfloat16* __restrict__ A, const __nv_bfloat16* __restrict__ Bkm,
    const float* __restrict__ bias, float* __restrict__ C,
    int ldC, int Nreal, int K3, int ldB, int mofs)
{
    __shared__ __nv_bfloat16 As[3][128 * 40];
    __shared__ __nv_bfloat16 Bs[3][32 * 72];
    const int tid = threadIdx.x;
    const int wid = tid >> 5, lane = tid & 31;
    const int gid = lane >> 2, tig = lane & 3;
    const int wm = wid & 3, wn = wid >> 2;
    const int m0 = blockIdx.y * 128;
    const int n0 = blockIdx.x * 64 + ((MODE == 1) ? ldC : 0);

    const uint32_t asBase = (uint32_t)__cvta_generic_to_shared(&As[0][0]);
    const uint32_t bsBase = (uint32_t)__cvta_generic_to_shared(&Bs[0][0]);
    const int lquad = lane >> 3, l7 = lane & 7, l15 = lane & 15;
    const uint32_t aLane = (uint32_t)((((lquad & 1) * 8 + l7) * 80) + (lquad >> 1) * 16);

    float acc[2][4][4] = {};
    const int nkt = K3 >> 5;

    const int rowA0 = tid >> 2,          cA0 = tid & 3;
    const int rowA1 = (tid + 256) >> 2;
    const int rB = tid >> 3,             cB = tid & 7;
    const int ga0 = m0 + rowA0, ga1 = m0 + rowA1;

    const uint32_t dA0 = asBase + (uint32_t)((rowA0 * 40 + cA0 * 8) * 2);
    const uint32_t dA1 = asBase + (uint32_t)((rowA1 * 40 + cA0 * 8) * 2);
    const uint32_t dB  = bsBase + (uint32_t)((rB * 72 + cB * 8) * 2);
    const uint32_t stA = 128 * 40 * 2, stB = 32 * 72 * 2;

    auto issue = [&](int kt, int buf) {
        cp16(dA0 + buf * stA, &A[(size_t)ga0 * K3 + kt * 32 + cA0 * 8]);
        cp16(dA1 + buf * stA, &A[(size_t)ga1 * K3 + kt * 32 + cA0 * 8]);
        cp16(dB  + buf * stB, &Bkm[(size_t)(kt * 32 + rB) * ldB + n0 + cB * 8]);
    };

    issue(0, 0); cp_commit();
    if (nkt > 1) issue(1, 1);
    cp_commit();

    for (int kt = 0; kt < nkt; kt++) {
        const int buf = kt % 3;
        if (kt + 2 < nkt) issue(kt + 2, (kt + 2) % 3);
        cp_commit();
        cp_wait<2>();
        __syncthreads();
#pragma unroll
        for (int ks = 0; ks < 2; ks++) {
            uint32_t a[2][4], b[4][2];
#pragma unroll
            for (int mi = 0; mi < 2; mi++)
                ldsm_x4(a[mi], asBase + (uint32_t)(buf * stA) +
                               (uint32_t)((wm * 32 + mi * 16) * 80 + ks * 32) + aLane);
#pragma unroll
            for (int ni = 0; ni < 4; ni++)
                ldsm_x2_trans(b[ni], bsBase + (uint32_t)(buf * stB) +
                              (uint32_t)(((ks * 16 + l15) * 72 + (wn * 32 + ni * 8)) * 2));
#pragma unroll
            for (int mi = 0; mi < 2; mi++)
#pragma unroll
                for (int ni = 0; ni < 4; ni++)
                    mma_bf16(acc[mi][ni], a[mi], b[ni]);
        }
        __syncthreads();
    }

#pragma unroll
    for (int mi = 0; mi < 2; mi++)
#pragma unroll
        for (int ni = 0; ni < 4; ni++) {
            int gm0 = m0 + wm * 32 + mi * 16 + gid;
            int gc0 = n0 + wn * 32 + ni * 8 + tig * 2;
#pragma unroll
            for (int e = 0; e < 4; e++) {
                int gm = gm0 + (e >> 1) * 8;
                int gc = gc0 + (e & 1);
                float v = acc[mi][ni][e];
                if (MODE == 1) {
                    if (gc < Nreal) {
                        int gg = mofs + gm;
                        int bb = gg & 31, tt = gg >> 5;
                        C[(size_t)(bb * T_ + tt) * Nreal + gc] = v + bias[gc];
                    }
                } else {
                    C[(size_t)gm * ldC + gc] = v + bias[gc];
                }
            }
        }
}

// ---------------- fused recurrence step (split-K z=ZN) ----------------
template<int BN, int TN, int NKC, int ZN, int GATE>
__global__ __launch_bounds__(128) void step_gemm(
    const float* __restrict__ A, const float* __restrict__ Bm,
    const float* __restrict__ xb, const float* __restrict__ hb,
    const float* __restrict__ hin, float* __restrict__ hout,
    float* __restrict__ extra, float* __restrict__ part,
    float* __restrict__ qout, unsigned int* __restrict__ ctr,
    int N, int K)
{
    constexpr int PB = (16 * BN) / 128;
    __shared__ float As[16][32];
    __shared__ float Bs[16][BN];
    __shared__ int doneflag;
    const int tid = threadIdx.x;
    const int tx = tid & 15, ty = tid >> 4;
    const int n0 = blockIdx.x * BN;
    const int z = blockIdx.z;
    const int k0 = z * NKC * 16;

    float pa[4], pb[PB];
    auto ldA = [&](int kt) {
#pragma unroll
        for (int i = 0; i < 4; i++) {
            int ii = tid + i * 128, k = ii & 15, m = ii >> 4;
            pa[i] = A[(size_t)m * K + k0 + kt * 16 + k];
        }
    };
    auto ldB = [&](int kt) {
#pragma unroll
        for (int i = 0; i < PB; i++) {
            int ii = tid + i * 128, k = ii / BN, n = ii - k * BN;
            pb[i] = Bm[(size_t)(k0 + kt * 16 + k) * N + n0 + n];
        }
    };

    float acc[4][TN];
#pragma unroll
    for (int i = 0; i < 4; i++)
#pragma unroll
        for (int j = 0; j < TN; j++) acc[i][j] = 0.f;

    ldA(0); ldB(0);
    for (int kt = 0; kt < NKC; kt++) {
#pragma unroll
        for (int i = 0; i < 4; i++) {
            int ii = tid + i * 128;
            As[ii & 15][ii >> 4] = pa[i];
        }
#pragma unroll
        for (int i = 0; i < PB; i++) {
            int ii = tid + i * 128, k = ii / BN;
            Bs[k][ii - k * BN] = pb[i];
        }
        __syncthreads();
        if (kt + 1 < NKC) { ldA(kt + 1); ldB(kt + 1); }
#pragma unroll
        for (int kk = 0; kk < 16; kk++) {
            float4 av = *reinterpret_cast<const float4*>(&As[kk][ty * 4]);
            float a[4] = {av.x, av.y, av.z, av.w};
#pragma unroll
            for (int j = 0; j < TN; j++) {
                float bv = Bs[kk][tx * TN + j];
#pragma unroll
                for (int i = 0; i < 4; i++) acc[i][j] += a[i] * bv;
            }
        }
        __syncthreads();
    }
#pragma unroll
    for (int i = 0; i < 4; i++) {
        int gm = ty * 4 + i;
#pragma unroll
        for (int j = 0; j < TN; j++)
            part[((size_t)(z * 32 + gm)) * N + n0 + tx * TN + j] = acc[i][j];
    }
    __threadfence();
    __syncthreads();
    if (tid == 0) {
        unsigned int prev = atomicAdd(&ctr[blockIdx.x], 1u);
        doneflag = (prev == (unsigned)(ZN - 1));
        if (prev == (unsigned)(ZN - 1)) ctr[blockIdx.x] = 0u;
    }
    __syncthreads();
    if (!doneflag) return;
    __threadfence();

    if (GATE == 0) {
#pragma unroll
        for (int i = 0; i < 16; i++) {
            int idx = tid + i * 128;
            int b = idx & 31, nl = idx >> 5;
            int n = n0 + nl;
            float s = 0.f;
#pragma unroll
            for (int zz = 0; zz < ZN; zz++) s += part[((size_t)(zz * 32 + b)) * N + n];
            qout[b * U_ + n] = s + hb[n];
        }
    } else {
        const int u0 = n0 / 3;
#pragma unroll
        for (int i = 0; i < 4; i++) {
            int idx = tid + i * 128;
            int b = idx & 31, ul = idx >> 5;
            int u = u0 + ul;
            float g[3];
#pragma unroll
            for (int gg = 0; gg < 3; gg++) {
                float s = 0.f;
#pragma unroll
                for (int zz = 0; zz < ZN; zz++)
                    s += part[((size_t)(zz * 32 + b)) * N + n0 + ul * 3 + gg];
                g[gg] = s;
            }
            float h;
            if (GATE == 1) {
                const float* gx = xb + (size_t)b * G_;
                float zg = sigm(gx[u] + g[0] + hb[u]);
                float rg = sigm(gx[U_ + u] + g[1] + hb[U_ + u]);
                float cg = tanhf(gx[2 * U_ + u] + rg * (g[2] + hb[2 * U_ + u]));
                h = zg * hin[b * U_ + u] + (1.f - zg) * cg;
                hout[b * U_ + u] = h;
                extra[(size_t)b * (S_ * U_) + u] = h;
            } else {
                const float* de = hin + (size_t)b * G_ + n0 + ul * 3;
                float zg = sigm(g[0] + de[0] + xb[u] + hb[u]);
                float rg = sigm(g[1] + de[1] + xb[U_ + u] + hb[U_ + u]);
                float cg = tanhf(g[2] + de[2] + xb[2 * U_ + u] + rg * hb[2 * U_ + u]);
                h = (1.f - zg) * cg;
                hout[b * U_ + u] = h;
                extra[(size_t)b * U_ + u] = h;
            }
        }
    }
}

// ---------------- attention + context ----------------
__global__ void attn_ctx(const float* __restrict__ Va, const float* __restrict__ bvp)
{
    const int b = blockIdx.x, tid = threadIdx.x;
    __shared__ float qs[U_];
    __shared__ float sc[S_];

    for (int u = tid; u < U_; u += 512) qs[u] = d_q[b * U_ + u];
    __syncthreads();

    const int w = tid >> 5, lane = tid & 31;
    for (int s = w; s < S_; s += 16) {
        const float* pr = d_pre + (size_t)b * (S_ * U_) + (size_t)s * U_;
        float p = 0.f;
        for (int u = lane; u < U_; u += 32) p += tanhf(pr[u] + qs[u]) * Va[u];
#pragma unroll
        for (int o = 16; o > 0; o >>= 1) p += __shfl_xor_sync(0xffffffffu, p, o);
        if (lane == 0) sc[s] = p + bvp[0];
    }
    __syncthreads();

    if (tid < 32) {
        float v0 = sc[tid], v1 = sc[tid + 32];
        float m = fmaxf(v0, v1);
#pragma unroll
        for (int o = 16; o > 0; o >>= 1) m = fmaxf(m, __shfl_xor_sync(0xffffffffu, m, o));
        float e0 = expf(v0 - m), e1 = expf(v1 - m);
        float s = e0 + e1;
#pragma unroll
        for (int o = 16; o > 0; o >>= 1) s += __shfl_xor_sync(0xffffffffu, s, o);
        float inv = 1.f / s;
        sc[tid] = e0 * inv; sc[tid + 32] = e1 * inv;
    }
    __syncthreads();

    for (int u = tid; u < U_; u += 512) {
        float a = 0.f;
        const float* eb = d_enc + (size_t)b * (S_ * U_) + u;
#pragma unroll 8
        for (int s = 0; s < S_; s++) a += sc[s] * eb[(size_t)s * U_];
        d_xcat[(size_t)b * U_ + u] = a;
    }
}

// ---------------- per-chunk argmax (rows b*16 + tbase + j, j in 0..3) ----------------
__global__ void argmax_part(const float* __restrict__ logits, long long* outI, float* outF,
                            int asFloat, int tbase)
{
    const int b = blockIdx.x >> 2, tt = tbase + (blockIdx.x & 3);
    const int row = b * T_ + tt;
    const float* p = logits + (size_t)row * V_;
    const int tid = threadIdx.x;
    float best = -INFINITY; int bi = 0;
    for (int v = tid; v < V_; v += 256) {
        float val = p[v];
        if (val > best) { best = val; bi = v; }
    }
    __shared__ float bvs[256]; __shared__ int bis[256];
    bvs[tid] = best; bis[tid] = bi;
    __syncthreads();
    for (int st = 128; st > 0; st >>= 1) {
        if (tid < st) {
            float ov = bvs[tid + st]; int oi = bis[tid + st];
            if (ov > bvs[tid] || (ov == bvs[tid] && oi < bis[tid])) { bvs[tid] = ov; bis[tid] = oi; }
        }
        __syncthreads();
    }
    if (tid == 0) {
        if (asFloat) outF[row] = (float)bis[0];
        else         outI[row] = (long long)bis[0];
    }
}

// ---------------- launcher ----------------
static float* symaddr(const void* sym) {
    void* p = nullptr;
    cudaGetSymbolAddress(&p, sym);
    return (float*)p;
}

extern "C" void kernel_launch(void* const* d_in, const int* in_sizes, int n_in,
                              void* d_out, int out_size)
{
    static cudaStream_t s2 = nullptr;
    static cudaEvent_t ev[16];
    if (!s2) {
        cudaStreamCreateWithFlags(&s2, cudaStreamNonBlocking);
        for (int i = 0; i < 16; i++) cudaEventCreateWithFlags(&ev[i], cudaEventDisableTiming);
    }

    const int s0 = (n_in >= 22) ? 4 : 2;
    const int*   enc_in  = (const int*)d_in[0];
    const int*   teacher = (const int*)d_in[1];
    const float* Ee      = (const float*)d_in[s0 + 0];
    const float* eWx     = (const float*)d_in[s0 + 1];
    const float* eWh     = (const float*)d_in[s0 + 2];
    const float* eb_in   = (const float*)d_in[s0 + 3];
    const float* eb_rec  = (const float*)d_in[s0 + 4];
    const float* Ed      = (const float*)d_in[s0 + 5];
    const float* dWx     = (const float*)d_in[s0 + 6];
    const float* db_in   = (const float*)d_in[s0 + 8];
    const float* db_rec  = (const float*)d_in[s0 + 9];
    const float* W1      = (const float*)d_in[s0 + 10];
    const float* b1      = (const float*)d_in[s0 + 11];
    const float* W2      = (const float*)d_in[s0 + 12];
    const float* b2      = (const float*)d_in[s0 + 13];
    const float* Va      = (const float*)d_in[s0 + 14];
    const float* bvp     = (const float*)d_in[s0 + 15];
    const float* Wf      = (const float*)d_in[s0 + 16];
    const float* bf      = (const float*)d_in[s0 + 17];

    float* hbase = symaddr(d_hbuf);
    float* hdec  = symaddr(d_hdec);
    float* encp  = symaddr(d_enc);
    float* prep  = symaddr(d_pre);
    float* qp    = symaddr(d_q);
    float* gpart = symaddr(d_gpart);
    float* xcat  = symaddr(d_xcat);
    float* demb  = symaddr(d_demb);
    float* Hall  = symaddr(d_Hall);
    float* lalt  = symaddr(d_logits_alt);
    float* gxall = symaddr(d_gxall);
    float* WhP   = symaddr(d_WhP);
    float* dWxP  = symaddr(d_dWxP);
    unsigned int* ctr; { void* p; cudaGetSymbolAddress(&p, d_ctr); ctr = (unsigned int*)p; }
    __nv_bfloat16* WfT3;  { void* p; cudaGetSymbolAddress(&p, d_WfT3);  WfT3  = (__nv_bfloat16*)p; }
    __nv_bfloat16* W1T3;  { void* p; cudaGetSymbolAddress(&p, d_W1T3);  W1T3  = (__nv_bfloat16*)p; }
    __nv_bfloat16* eWxT3; { void* p; cudaGetSymbolAddress(&p, d_eWxT3); eWxT3 = (__nv_bfloat16*)p; }
    __nv_bfloat16* xembS; { void* p; cudaGetSymbolAddress(&p, d_xembS); xembS = (__nv_bfloat16*)p; }
    __nv_bfloat16* encS;  { void* p; cudaGetSymbolAddress(&p, d_encS);  encS  = (__nv_bfloat16*)p; }
    __nv_bfloat16* HallS; { void* p; cudaGetSymbolAddress(&p, d_HallS); HallS = (__nv_bfloat16*)p; }

    const long long LOGN = (long long)B_ * T_ * V_;
    float* logits_dst = (float*)d_out;
    long long* predI = nullptr; float* predF = nullptr; int asFloat = 0;
    if ((long long)out_size == LOGN + 512) { predF = (float*)d_out + LOGN; asFloat = 1; }
    else if ((long long)out_size == LOGN + 1024) { predI = (long long*)((float*)d_out + LOGN); }
    else if (out_size == 512) { logits_dst = lalt; predI = (long long*)d_out; }
    const int needPred = (predI || predF) ? 1 : 0;

    cudaMemsetAsync(hbase, 0, (size_t)B_ * U_ * sizeof(float));

    // main stream front
    perm3<<<U_ * G_ / 256, 256>>>(eWh, WhP);
    conv_splitB_v8<<<(E_ * (G_ / 8) + 255) / 256, 256>>>(eWx, eWxT3, E_, G_, G_);
    embed_split<<<2048, 256>>>(enc_in, Ee);
    gemm_bf16<0><<<dim3(G_ / 64, 4), 256>>>(xembS, eWxT3, eb_in, gxall, G_, G_, 768, G_, 0);

    // encoder steps 0 and 1
    for (int s = 0; s < 2; s++) {
        float* hin  = hbase + (size_t)(s & 1) * B_ * U_;
        float* hout = hbase + (size_t)((s + 1) & 1) * B_ * U_;
        step_gemm<48,3,16,4,1><<<dim3(G_ / 48, 1, 4), 128>>>(
            hin, WhP, gxall + (size_t)s * B_ * G_, eb_rec,
            hin, hout, encp + (size_t)s * U_, gpart, nullptr, ctr, G_, U_);
    }

    // fork side stream: gx chunks 1-3, W1 split, dWx perm, demb (light work only)
    cudaEventRecord(ev[0], 0);
    cudaStreamWaitEvent(s2, ev[0], 0);
    for (int c = 1; c < 4; c++) {
        gemm_bf16<0><<<dim3(G_ / 64, 4), 256, 0, s2>>>(
            xembS + (size_t)c * 512 * 768, eWxT3, eb_in,
            gxall + (size_t)c * 512 * G_, G_, G_, 768, G_, 0);
        cudaEventRecord(ev[c], s2);
    }
    conv_splitB_v8<<<(U_ * (U_ / 8) + 255) / 256, 256, 0, s2>>>(W1, W1T3, U_, U_, U_);
    cudaEventRecord(ev[4], s2);                     // W1T3 ready
    perm3<<<(U_ + E_) * G_ / 256, 256, 0, s2>>>(dWx, dWxP);
    demb_gemm<<<dim3(G_ / 64, 16), 128, 0, s2>>>(Ed, teacher, dWxP, demb);
    cudaEventRecord(ev[5], s2);                     // dWxP + demb ready

    // encoder steps 2..63
    for (int s = 2; s < S_; s++) {
        if ((s & 15) == 0) cudaStreamWaitEvent(0, ev[s >> 4], 0);
        float* hin  = hbase + (size_t)(s & 1) * B_ * U_;
        float* hout = hbase + (size_t)((s + 1) & 1) * B_ * U_;
        step_gemm<48,3,16,4,1><<<dim3(G_ / 48, 1, 4), 128>>>(
            hin, WhP, gxall + (size_t)s * B_ * G_, eb_rec,
            hin, hout, encp + (size_t)s * U_, gpart, nullptr, ctr, G_, U_);
    }

    // encS split (main); then pre_enc halves on main + s2; Wf split on s2 after
    conv_splitA<<<(B_ * S_ * U_) / 256, 256>>>(encp, encS);
    cudaEventRecord(ev[6], 0);                      // encS ready
    cudaStreamWaitEvent(0, ev[4], 0);
    gemm_bf16<0><<<dim3(U_ / 64, 8), 256>>>(encS, W1T3, b1, prep, U_, U_, 3072, U_, 0);
    cudaStreamWaitEvent(s2, ev[6], 0);
    gemm_bf16<0><<<dim3(U_ / 64, 8), 256, 0, s2>>>(encS + (size_t)1024 * 3072, W1T3, b1,
                                                   prep + (size_t)1024 * U_, U_, U_, 3072, U_, 0);
    cudaEventRecord(ev[7], s2);                     // pre half B ready
    conv_splitB_v8<<<(U_ * (VP_ / 8) + 255) / 256, 256, 0, s2>>>(Wf, WfT3, U_, V_, VP_);

    // decoder
    cudaStreamWaitEvent(0, ev[5], 0);
    cudaStreamWaitEvent(0, ev[7], 0);
    for (int t = 0; t < T_; t++) {
        const float* hd = (t == 0) ? hbase : hdec;
        step_gemm<64,4,16,4,0><<<dim3(U_ / 64, 1, 4), 128>>>(
            hd, W2, nullptr, b2, nullptr, nullptr, nullptr, gpart, qp, ctr + 64, U_, U_);
        attn_ctx<<<B_, 512>>>(Va, bvp);
        step_gemm<48,3,16,4,2><<<dim3(G_ / 48, 1, 4), 128>>>(
            xcat, dWxP, db_in, db_rec, demb + (size_t)t * 32 * G_, hdec,
            Hall + (size_t)t * B_ * U_, gpart, nullptr, ctr + 128, G_, U_);
        if ((t & 3) == 3 && t < 15) {
            int c = t >> 2;                         // chunks 0,1,2 on s2
            cudaEventRecord(ev[8 + c], 0);
            cudaStreamWaitEvent(s2, ev[8 + c], 0);
            conv_splitA<<<512, 256, 0, s2>>>(Hall + (size_t)c * 128 * U_,
                                             HallS + (size_t)c * 128 * 3072);
            gemm_bf16<1><<<dim3(VP_ / 64, 1), 256, 0, s2>>>(
                HallS + (size_t)c * 128 * 3072, WfT3, bf, logits_dst, 0, V_, 3072, VP_, c * 128);
            if (needPred)
                argmax_part<<<128, 256, 0, s2>>>(logits_dst, predI, predF, asFloat, 4 * c);
        }
    }

    // final chunk (c=3): conv on main, gemm split N-wise across main + s2
    conv_splitA<<<512, 256>>>(Hall + (size_t)3 * 128 * U_, HallS + (size_t)3 * 128 * 3072);
    cudaEventRecord(ev[11], 0);
    gemm_bf16<1><<<dim3(158, 1), 256>>>(
        HallS + (size_t)3 * 128 * 3072, WfT3, bf, logits_dst, 0, V_, 3072, VP_, 384);
    cudaStreamWaitEvent(s2, ev[11], 0);
    gemm_bf16<1><<<dim3(158, 1), 256, 0, s2>>>(
        HallS + (size_t)3 * 128 * 3072, WfT3, bf, logits_dst, 10112, V_, 3072, VP_, 384);
    cudaEventRecord(ev[12], s2);
    cudaStreamWaitEvent(0, ev[12], 0);
    if (needPred) argmax_part<<<128, 256>>>(logits_dst, predI, predF, asFloat, 12);
}